// round 4
// baseline (speedup 1.0000x reference)
#include <cuda_runtime.h>

#define Bb 2
#define Ss 2048
#define DM 1024
#define Hh 16
#define HD 64
#define NROWS (Bb*Ss)

// Scratch (device globals — no allocations allowed)
__device__ float g_Q[Bb*Hh*Ss*HD];   // [B,H,S,64]
__device__ float g_K[Bb*Hh*Ss*HD];
__device__ float g_V[Bb*Hh*Ss*HD];
__device__ float g_att[NROWS*DM];    // attention output, [B,S, H*64]

// ---------------------------------------------------------------------------
// GEMM: C = X[NROWS,DM] @ W[DM,DM] + bias
// MODE 0: C row-major [NROWS, DM]
// MODE 1: remap output column n -> head h=n/64, d=n%64; store [B,H,S,64]
// Tiles: 128x128x16, 256 threads, 8x8 micro-tile per thread.
// ---------------------------------------------------------------------------
template <int MODE>
__global__ __launch_bounds__(256) void gemm_kernel(
    const float* __restrict__ X, const float* __restrict__ W,
    const float* __restrict__ bias, float* __restrict__ C)
{
    __shared__ float sX[16][132];   // transposed: sX[k][m]
    __shared__ float sW[16][132];   // sW[k][n]

    const int tid = threadIdx.x;
    const int tx = tid & 15;
    const int ty = tid >> 4;
    const int m0 = blockIdx.y * 128;
    const int n0 = blockIdx.x * 128;

    float acc[8][8];
#pragma unroll
    for (int i = 0; i < 8; i++)
#pragma unroll
        for (int j = 0; j < 8; j++) acc[i][j] = 0.f;

    for (int k0 = 0; k0 < DM; k0 += 16) {
        // load X tile (128 rows x 16 cols), store transposed
#pragma unroll
        for (int r = 0; r < 2; r++) {
            int idx = tid + r * 256;          // 0..511
            int m   = idx >> 2;               // 0..127
            int c   = (idx & 3) << 2;         // 0,4,8,12
            float4 v = *(const float4*)&X[(m0 + m) * DM + k0 + c];
            sX[c + 0][m] = v.x; sX[c + 1][m] = v.y;
            sX[c + 2][m] = v.z; sX[c + 3][m] = v.w;
        }
        // load W tile (16 rows x 128 cols)
#pragma unroll
        for (int r = 0; r < 2; r++) {
            int idx = tid + r * 256;
            int k   = idx >> 5;               // 0..15
            int c   = (idx & 31) << 2;        // 0..124
            *(float4*)&sW[k][c] = *(const float4*)&W[(k0 + k) * DM + n0 + c];
        }
        __syncthreads();

#pragma unroll
        for (int k = 0; k < 16; k++) {
            float a[8], b[8];
            *(float4*)&a[0] = *(float4*)&sX[k][ty * 8];
            *(float4*)&a[4] = *(float4*)&sX[k][ty * 8 + 4];
            *(float4*)&b[0] = *(float4*)&sW[k][tx * 8];
            *(float4*)&b[4] = *(float4*)&sW[k][tx * 8 + 4];
#pragma unroll
            for (int i = 0; i < 8; i++)
#pragma unroll
                for (int j = 0; j < 8; j++)
                    acc[i][j] += a[i] * b[j];
        }
        __syncthreads();
    }

#pragma unroll
    for (int i = 0; i < 8; i++) {
        int m = m0 + ty * 8 + i;
#pragma unroll
        for (int j = 0; j < 8; j++) {
            int n = n0 + tx * 8 + j;
            float val = acc[i][j] + bias[n];
            if (MODE == 0) {
                C[m * DM + n] = val;
            } else {
                int b_ = m / Ss, s_ = m - b_ * Ss;
                int h_ = n >> 6, d_ = n & 63;
                C[((b_ * Hh + h_) * Ss + s_) * HD + d_] = val;
            }
        }
    }
}

// ---------------------------------------------------------------------------
// Flash attention (causal), fp32. One CTA = one (b,h,64-row q tile).
// 256 threads as 16x16; thread owns 4 q-rows (ty*4+i) x 4 cols/dims (tx*4+j).
// Smem (dynamic): sQt[64][64] (d-major), sKt[64][64] (d-major),
//                 sV[64][64] (k-major), sP[64][65].
// P/PV reuse stays within one warp per 4-row group -> __syncwarp suffices there.
// ---------------------------------------------------------------------------
#define FLASH_SMEM_FLOATS (4096 + 4096 + 4096 + 64 * 65)
#define FLASH_SMEM_BYTES  (FLASH_SMEM_FLOATS * 4)

__global__ __launch_bounds__(256) void flash_kernel(
    const float* __restrict__ Q, const float* __restrict__ K,
    const float* __restrict__ V, float* __restrict__ OUT)
{
    extern __shared__ float smem[];
    float* sQt = smem;             // [d][r] stride 64
    float* sKt = smem + 4096;      // [d][c] stride 64
    float* sV  = smem + 8192;      // [k][d] stride 64
    float* sP  = smem + 12288;     // [r][k] stride 65

    const int tid = threadIdx.x;
    const int tx = tid & 15;
    const int ty = tid >> 4;
    const int qi = blockIdx.x;            // 0..31
    const int bh = blockIdx.y;            // 0..31
    const int b_ = bh / Hh;
    const int h_ = bh - b_ * Hh;
    const int s0 = qi * 64;

    const float* Qb = Q + ((size_t)bh * Ss + s0) * HD;

    // load Q tile transposed
#pragma unroll
    for (int it = 0; it < 4; it++) {
        int idx = tid + it * 256;         // 0..1023
        int r = idx >> 4;                 // 0..63
        int c = (idx & 15) << 2;          // 0..60
        float4 v = *(const float4*)&Qb[r * HD + c];
        sQt[(c + 0) * 64 + r] = v.x;
        sQt[(c + 1) * 64 + r] = v.y;
        sQt[(c + 2) * 64 + r] = v.z;
        sQt[(c + 3) * 64 + r] = v.w;
    }

    float m_i[4], l_i[4], o[4][4];
#pragma unroll
    for (int i = 0; i < 4; i++) {
        m_i[i] = -1e30f; l_i[i] = 0.f;
#pragma unroll
        for (int j = 0; j < 4; j++) o[i][j] = 0.f;
    }

    for (int kt = 0; kt <= qi; kt++) {
        __syncthreads();
        const float* Kb = K + ((size_t)bh * Ss + kt * 64) * HD;
        const float* Vb = V + ((size_t)bh * Ss + kt * 64) * HD;
#pragma unroll
        for (int it = 0; it < 4; it++) {
            int idx = tid + it * 256;
            int r = idx >> 4;
            int c = (idx & 15) << 2;
            float4 v = *(const float4*)&Kb[r * HD + c];
            sKt[(c + 0) * 64 + r] = v.x;
            sKt[(c + 1) * 64 + r] = v.y;
            sKt[(c + 2) * 64 + r] = v.z;
            sKt[(c + 3) * 64 + r] = v.w;
            *(float4*)&sV[r * 64 + c] = *(const float4*)&Vb[r * HD + c];
        }
        __syncthreads();

        // ---- S = Q K^T (64x64 tile, 4x4 per thread) ----
        float s[4][4];
#pragma unroll
        for (int i = 0; i < 4; i++)
#pragma unroll
            for (int j = 0; j < 4; j++) s[i][j] = 0.f;

#pragma unroll 16
        for (int d = 0; d < 64; d++) {
            float4 a = *(float4*)&sQt[d * 64 + ty * 4];
            float4 c = *(float4*)&sKt[d * 64 + tx * 4];
            float av[4] = {a.x, a.y, a.z, a.w};
            float cv[4] = {c.x, c.y, c.z, c.w};
#pragma unroll
            for (int i = 0; i < 4; i++)
#pragma unroll
                for (int j = 0; j < 4; j++)
                    s[i][j] += av[i] * cv[j];
        }

        const bool diag = (kt == qi);
#pragma unroll
        for (int i = 0; i < 4; i++) {
            int qrow = ty * 4 + i;            // local == global offset (same tile idx)
#pragma unroll
            for (int j = 0; j < 4; j++) {
                s[i][j] *= 0.03125f;          // 1/sqrt(1024)
                if (diag && (tx * 4 + j) > qrow) s[i][j] -= 1e9f;
            }
        }

        // ---- online softmax (row reductions across the 16 tx lanes) ----
#pragma unroll
        for (int i = 0; i < 4; i++) {
            float mr = fmaxf(fmaxf(s[i][0], s[i][1]), fmaxf(s[i][2], s[i][3]));
#pragma unroll
            for (int off = 1; off < 16; off <<= 1)
                mr = fmaxf(mr, __shfl_xor_sync(0xffffffffu, mr, off));
            float mn = fmaxf(m_i[i], mr);
            float corr = __expf(m_i[i] - mn);
            float p[4], rs = 0.f;
#pragma unroll
            for (int j = 0; j < 4; j++) { p[j] = __expf(s[i][j] - mn); rs += p[j]; }
#pragma unroll
            for (int off = 1; off < 16; off <<= 1)
                rs += __shfl_xor_sync(0xffffffffu, rs, off);
            l_i[i] = l_i[i] * corr + rs;
            m_i[i] = mn;
#pragma unroll
            for (int j = 0; j < 4; j++) {
                o[i][j] *= corr;
                sP[(ty * 4 + i) * 65 + tx * 4 + j] = p[j];
            }
        }
        __syncwarp();

        // ---- O += P V ----
#pragma unroll 8
        for (int k = 0; k < 64; k++) {
            float4 vv = *(float4*)&sV[k * 64 + tx * 4];
#pragma unroll
            for (int i = 0; i < 4; i++) {
                float pa = sP[(ty * 4 + i) * 65 + k];
                o[i][0] += pa * vv.x;
                o[i][1] += pa * vv.y;
                o[i][2] += pa * vv.z;
                o[i][3] += pa * vv.w;
            }
        }
        __syncwarp();
    }

    // write [B,S, h*64+d]
#pragma unroll
    for (int i = 0; i < 4; i++) {
        float inv = 1.0f / l_i[i];
        int row = s0 + ty * 4 + i;
        float4 r4;
        r4.x = o[i][0] * inv; r4.y = o[i][1] * inv;
        r4.z = o[i][2] * inv; r4.w = o[i][3] * inv;
        *(float4*)&OUT[((size_t)b_ * Ss + row) * DM + h_ * HD + tx * 4] = r4;
    }
}

// ---------------------------------------------------------------------------
extern "C" void kernel_launch(void* const* d_in, const int* in_sizes, int n_in,
                              void* d_out, int out_size)
{
    const float* queries = (const float*)d_in[0];
    const float* keys    = (const float*)d_in[1];
    const float* values  = (const float*)d_in[2];
    // d_in[3] = mask (causal triu) — computed arithmetically instead
    const float* Wq = (const float*)d_in[4];
    const float* bq = (const float*)d_in[5];
    const float* Wk = (const float*)d_in[6];
    const float* bk = (const float*)d_in[7];
    const float* Wv = (const float*)d_in[8];
    const float* bv = (const float*)d_in[9];
    const float* Wo = (const float*)d_in[10];
    const float* bo = (const float*)d_in[11];

    // One-time host-side setup: cache scratch pointers + set smem attribute.
    // (Caches pointers only — every call still enqueues the identical work.)
    static float *qs = nullptr, *ks = nullptr, *vs = nullptr, *att = nullptr;
    if (qs == nullptr) {
        cudaGetSymbolAddress((void**)&qs,  g_Q);
        cudaGetSymbolAddress((void**)&ks,  g_K);
        cudaGetSymbolAddress((void**)&vs,  g_V);
        cudaGetSymbolAddress((void**)&att, g_att);
        cudaFuncSetAttribute(flash_kernel,
                             cudaFuncAttributeMaxDynamicSharedMemorySize,
                             FLASH_SMEM_BYTES);
    }

    dim3 ggrid(DM / 128, NROWS / 128);   // (8, 32)
    gemm_kernel<1><<<ggrid, 256>>>(queries, Wq, bq, qs);
    gemm_kernel<1><<<ggrid, 256>>>(keys,    Wk, bk, ks);
    gemm_kernel<1><<<ggrid, 256>>>(values,  Wv, bv, vs);

    flash_kernel<<<dim3(Ss / 64, Bb * Hh), 256, FLASH_SMEM_BYTES>>>(qs, ks, vs, att);

    gemm_kernel<0><<<ggrid, 256>>>(att, Wo, bo, (float*)d_out);
}

// round 11
// speedup vs baseline: 1.4131x; 1.4131x over previous
#include <cuda_runtime.h>
#include <cuda_bf16.h>
#include <cstdint>

#define Bb 2
#define Ss 2048
#define DM 1024
#define Hh 16
#define HD 64
#define NROWS (Bb*Ss)

// ---------------------------------------------------------------------------
// Scratch (device globals — no allocations allowed)
// ---------------------------------------------------------------------------
__device__ float g_Q[Bb*Hh*Ss*HD];          // [B,H,S,64]
__device__ float g_K[Bb*Hh*Ss*HD];
__device__ float g_V[Bb*Hh*Ss*HD];
__device__ float g_att[NROWS*DM];           // attention output, [B,S, H*64]
__device__ __nv_bfloat16 g_Ahi[NROWS*DM];   // split activations (reused per GEMM)
__device__ __nv_bfloat16 g_Alo[NROWS*DM];
__device__ __nv_bfloat16 g_Bhi[DM*DM];      // split+transposed weights [n][k]
__device__ __nv_bfloat16 g_Blo[DM*DM];

// Single dynamic-smem symbol shared by all kernels (type must agree TU-wide)
extern __shared__ char dyn_smem[];

// ---------------------------------------------------------------------------
// Helpers
// ---------------------------------------------------------------------------
__device__ __forceinline__ uint32_t smem_to_u32(const void* p) {
    uint32_t a;
    asm("{ .reg .u64 t; cvta.to.shared.u64 t, %1; cvt.u32.u64 %0, t; }"
        : "=r"(a) : "l"(p));
    return a;
}
__device__ __forceinline__ uint32_t swz128(uint32_t o) {
    return o ^ ((o >> 3) & 0x70);
}
__device__ __forceinline__ void ldsm4(uint32_t* r, uint32_t addr) {
    asm volatile("ldmatrix.sync.aligned.m8n8.x4.shared.b16 {%0,%1,%2,%3}, [%4];"
                 : "=r"(r[0]), "=r"(r[1]), "=r"(r[2]), "=r"(r[3]) : "r"(addr));
}
// D (+)= A(m16k16,row) * B(k16n8,col) ; bf16 in, fp32 accum
__device__ __forceinline__ void mma_bf16(float* d, const uint32_t* a,
                                         const uint32_t b0, const uint32_t b1) {
    asm volatile(
        "mma.sync.aligned.m16n8k16.row.col.f32.bf16.bf16.f32 "
        "{%0,%1,%2,%3}, {%4,%5,%6,%7}, {%8,%9}, {%0,%1,%2,%3};"
        : "+f"(d[0]), "+f"(d[1]), "+f"(d[2]), "+f"(d[3])
        : "r"(a[0]), "r"(a[1]), "r"(a[2]), "r"(a[3]), "r"(b0), "r"(b1));
}

// ---------------------------------------------------------------------------
// Conversion kernels: fp32 -> bf16 hi/lo split
// ---------------------------------------------------------------------------
__global__ __launch_bounds__(256) void conv_split(
    const float* __restrict__ X, __nv_bfloat16* __restrict__ Hi,
    __nv_bfloat16* __restrict__ Lo, int n4)
{
    int i = blockIdx.x * 256 + threadIdx.x;
    if (i >= n4) return;
    float4 v = ((const float4*)X)[i];
    __nv_bfloat16 h0 = __float2bfloat16(v.x), h1 = __float2bfloat16(v.y);
    __nv_bfloat16 h2 = __float2bfloat16(v.z), h3 = __float2bfloat16(v.w);
    __nv_bfloat16 l0 = __float2bfloat16(v.x - __bfloat162float(h0));
    __nv_bfloat16 l1 = __float2bfloat16(v.y - __bfloat162float(h1));
    __nv_bfloat16 l2 = __float2bfloat16(v.z - __bfloat162float(h2));
    __nv_bfloat16 l3 = __float2bfloat16(v.w - __bfloat162float(h3));
    __nv_bfloat162 ha(h0, h1), hb(h2, h3), la(l0, l1), lb(l2, l3);
    uint2 hu, lu;
    hu.x = *(uint32_t*)&ha; hu.y = *(uint32_t*)&hb;
    lu.x = *(uint32_t*)&la; lu.y = *(uint32_t*)&lb;
    *(uint2*)(Hi + 4 * (size_t)i) = hu;
    *(uint2*)(Lo + 4 * (size_t)i) = lu;
}

// W[k][n] fp32 -> out[n][k] bf16 hi/lo (transpose + split)
__global__ __launch_bounds__(256) void conv_w_t(
    const float* __restrict__ W, __nv_bfloat16* __restrict__ Hi,
    __nv_bfloat16* __restrict__ Lo)
{
    __shared__ float t[32][33];
    const int tx = threadIdx.x, ty = threadIdx.y;           // 32 x 8
    const int n0 = blockIdx.x * 32, k0 = blockIdx.y * 32;
#pragma unroll
    for (int r = ty; r < 32; r += 8)
        t[r][tx] = W[(size_t)(k0 + r) * DM + n0 + tx];
    __syncthreads();
#pragma unroll
    for (int r = ty; r < 32; r += 8) {
        float v = t[tx][r];                                  // W[k0+tx][n0+r]
        __nv_bfloat16 h = __float2bfloat16(v);
        __nv_bfloat16 l = __float2bfloat16(v - __bfloat162float(h));
        size_t o = (size_t)(n0 + r) * DM + k0 + tx;
        Hi[o] = h; Lo[o] = l;
    }
}

// ---------------------------------------------------------------------------
// mma.sync GEMM: C[m][n] = sum_k A[m][k]*W[k][n] + bias[n]
//   A split bf16 row-major [m][k]; B split bf16 [n][k] (= W^T).
//   3-MMA split accumulation: Ahi*Bhi + Ahi*Blo + Alo*Bhi, fp32 accum.
//   CTA tile 128x128, K-chunk 64 in SW128 smem, 8 warps x (32x64) warp tile.
// MODE 0: C row-major [NROWS,DM].  MODE 1: head-remapped [B,H,S,64].
// ---------------------------------------------------------------------------
#define G_SMEM_TOTAL 65536   // 4 x 16KB: Ahi, Alo, Bhi, Blo (128 rows x 128B)

template <int MODE>
__global__ __launch_bounds__(256, 1) void gemm_mma(
    const __nv_bfloat16* __restrict__ Ahi, const __nv_bfloat16* __restrict__ Alo,
    const __nv_bfloat16* __restrict__ Bhi, const __nv_bfloat16* __restrict__ Blo,
    const float* __restrict__ bias, float* __restrict__ C)
{
    char* smem = dyn_smem;
    const uint32_t sb = smem_to_u32(smem);
    const int tid = threadIdx.x;
    const int lane = tid & 31, wid = tid >> 5;
    const int wm = (wid >> 1) * 32;          // warp m offset: 0,32,64,96
    const int wn = (wid & 1) * 64;           // warp n offset: 0,64
    const int n0 = blockIdx.x * 128, m0 = blockIdx.y * 128;

    float acc[2][8][4];
#pragma unroll
    for (int mt = 0; mt < 2; mt++)
#pragma unroll
        for (int nt = 0; nt < 8; nt++)
#pragma unroll
            for (int c = 0; c < 4; c++) acc[mt][nt][c] = 0.f;

    const int lr = lane & 15;                 // ldmatrix row within 16
    const int lc = (lane >> 4) * 16;          // ldmatrix 16B col select

    for (int ch = 0; ch < DM / 64; ch++) {
        __syncthreads();
        // ---- load 4 buffers (each 128 rows x 128B) into swizzled smem ----
        {
            const uint4* srcs[4] = {
                (const uint4*)Ahi + (size_t)m0 * 128 + ch * 8,
                (const uint4*)Alo + (size_t)m0 * 128 + ch * 8,
                (const uint4*)Bhi + (size_t)n0 * 128 + ch * 8,
                (const uint4*)Blo + (size_t)n0 * 128 + ch * 8 };
#pragma unroll
            for (int bf = 0; bf < 4; bf++) {
                const uint4* src = srcs[bf];
                char* dst = smem + bf * 16384;
#pragma unroll
                for (int it = 0; it < 4; it++) {
                    int t = tid + it * 256;       // 0..1023
                    int r = t >> 3, c = t & 7;
                    uint4 v = src[(size_t)r * 128 + c];
                    *(uint4*)(dst + swz128(r * 128 + c * 16)) = v;
                }
            }
        }
        __syncthreads();

        // ---- 4 k-steps of 16 ----
#pragma unroll
        for (int kk = 0; kk < 4; kk++) {
            uint32_t ah[2][4], al[2][4], bh[8][2], bl[8][2];
#pragma unroll
            for (int mt = 0; mt < 2; mt++) {
                uint32_t off = (uint32_t)(wm + mt * 16 + lr) * 128 + kk * 32 + lc;
                uint32_t so = swz128(off);
                ldsm4(ah[mt], sb + so);
                ldsm4(al[mt], sb + 16384 + so);
            }
#pragma unroll
            for (int g = 0; g < 4; g++) {     // 16 n-rows per ldmatrix.x4
                uint32_t off = (uint32_t)(wn + g * 16 + lr) * 128 + kk * 32 + lc;
                uint32_t so = swz128(off);
                uint32_t t4[4];
                ldsm4(t4, sb + 32768 + so);
                bh[2*g][0] = t4[0]; bh[2*g][1] = t4[2];
                bh[2*g+1][0] = t4[1]; bh[2*g+1][1] = t4[3];
                ldsm4(t4, sb + 49152 + so);
                bl[2*g][0] = t4[0]; bl[2*g][1] = t4[2];
                bl[2*g+1][0] = t4[1]; bl[2*g+1][1] = t4[3];
            }
#pragma unroll
            for (int mt = 0; mt < 2; mt++)
#pragma unroll
                for (int nt = 0; nt < 8; nt++) {
                    mma_bf16(acc[mt][nt], ah[mt], bh[nt][0], bh[nt][1]);
                    mma_bf16(acc[mt][nt], ah[mt], bl[nt][0], bl[nt][1]);
                    mma_bf16(acc[mt][nt], al[mt], bh[nt][0], bh[nt][1]);
                }
        }
    }

    // ---- epilogue: c frag rows lane/4 (+8), cols (lane%4)*2 (+1) ----
#pragma unroll
    for (int mt = 0; mt < 2; mt++) {
#pragma unroll
        for (int half = 0; half < 2; half++) {
            int m = m0 + wm + mt * 16 + (lane >> 2) + half * 8;
            int b_ = m / Ss, s_ = m - b_ * Ss;
#pragma unroll
            for (int nt = 0; nt < 8; nt++) {
                int n = n0 + wn + nt * 8 + (lane & 3) * 2;
                float v0 = acc[mt][nt][half * 2 + 0] + bias[n];
                float v1 = acc[mt][nt][half * 2 + 1] + bias[n + 1];
                if (MODE == 0) {
                    C[(size_t)m * DM + n]     = v0;
                    C[(size_t)m * DM + n + 1] = v1;
                } else {
                    int h = n >> 6, d = n & 63;
                    size_t base = (((size_t)b_ * Hh + h) * Ss + s_) * HD + d;
                    C[base]     = v0;
                    C[base + 1] = v1;
                }
            }
        }
    }
}

// ---------------------------------------------------------------------------
// Flash attention (causal), fp32 — unchanged (isolating the GEMM change)
// ---------------------------------------------------------------------------
#define FLASH_SMEM_FLOATS (4096 + 4096 + 4096 + 64 * 65)
#define FLASH_SMEM_BYTES  (FLASH_SMEM_FLOATS * 4)

__global__ __launch_bounds__(256) void flash_kernel(
    const float* __restrict__ Q, const float* __restrict__ K,
    const float* __restrict__ V, float* __restrict__ OUT)
{
    float* smem = (float*)dyn_smem;
    float* sQt = smem;             // [d][r] stride 64
    float* sKt = smem + 4096;      // [d][c] stride 64
    float* sV  = smem + 8192;      // [k][d] stride 64
    float* sP  = smem + 12288;     // [r][k] stride 65

    const int tid = threadIdx.x;
    const int tx = tid & 15;
    const int ty = tid >> 4;
    const int qi = blockIdx.x;
    const int bh = blockIdx.y;
    const int b_ = bh / Hh;
    const int h_ = bh - b_ * Hh;
    const int s0 = qi * 64;

    const float* Qb = Q + ((size_t)bh * Ss + s0) * HD;

#pragma unroll
    for (int it = 0; it < 4; it++) {
        int idx = tid + it * 256;
        int r = idx >> 4;
        int c = (idx & 15) << 2;
        float4 v = *(const float4*)&Qb[r * HD + c];
        sQt[(c + 0) * 64 + r] = v.x;
        sQt[(c + 1) * 64 + r] = v.y;
        sQt[(c + 2) * 64 + r] = v.z;
        sQt[(c + 3) * 64 + r] = v.w;
    }

    float m_i[4], l_i[4], o[4][4];
#pragma unroll
    for (int i = 0; i < 4; i++) {
        m_i[i] = -1e30f; l_i[i] = 0.f;
#pragma unroll
        for (int j = 0; j < 4; j++) o[i][j] = 0.f;
    }

    for (int kt = 0; kt <= qi; kt++) {
        __syncthreads();
        const float* Kb = K + ((size_t)bh * Ss + kt * 64) * HD;
        const float* Vb = V + ((size_t)bh * Ss + kt * 64) * HD;
#pragma unroll
        for (int it = 0; it < 4; it++) {
            int idx = tid + it * 256;
            int r = idx >> 4;
            int c = (idx & 15) << 2;
            float4 v = *(const float4*)&Kb[r * HD + c];
            sKt[(c + 0) * 64 + r] = v.x;
            sKt[(c + 1) * 64 + r] = v.y;
            sKt[(c + 2) * 64 + r] = v.z;
            sKt[(c + 3) * 64 + r] = v.w;
            *(float4*)&sV[r * 64 + c] = *(const float4*)&Vb[r * HD + c];
        }
        __syncthreads();

        float s[4][4];
#pragma unroll
        for (int i = 0; i < 4; i++)
#pragma unroll
            for (int j = 0; j < 4; j++) s[i][j] = 0.f;

#pragma unroll 16
        for (int d = 0; d < 64; d++) {
            float4 a = *(float4*)&sQt[d * 64 + ty * 4];
            float4 c = *(float4*)&sKt[d * 64 + tx * 4];
            float av[4] = {a.x, a.y, a.z, a.w};
            float cv[4] = {c.x, c.y, c.z, c.w};
#pragma unroll
            for (int i = 0; i < 4; i++)
#pragma unroll
                for (int j = 0; j < 4; j++)
                    s[i][j] += av[i] * cv[j];
        }

        const bool diag = (kt == qi);
#pragma unroll
        for (int i = 0; i < 4; i++) {
            int qrow = ty * 4 + i;
#pragma unroll
            for (int j = 0; j < 4; j++) {
                s[i][j] *= 0.03125f;
                if (diag && (tx * 4 + j) > qrow) s[i][j] -= 1e9f;
            }
        }

#pragma unroll
        for (int i = 0; i < 4; i++) {
            float mr = fmaxf(fmaxf(s[i][0], s[i][1]), fmaxf(s[i][2], s[i][3]));
#pragma unroll
            for (int off = 1; off < 16; off <<= 1)
                mr = fmaxf(mr, __shfl_xor_sync(0xffffffffu, mr, off));
            float mn = fmaxf(m_i[i], mr);
            float corr = __expf(m_i[i] - mn);
            float p[4], rs = 0.f;
#pragma unroll
            for (int j = 0; j < 4; j++) { p[j] = __expf(s[i][j] - mn); rs += p[j]; }
#pragma unroll
            for (int off = 1; off < 16; off <<= 1)
                rs += __shfl_xor_sync(0xffffffffu, rs, off);
            l_i[i] = l_i[i] * corr + rs;
            m_i[i] = mn;
#pragma unroll
            for (int j = 0; j < 4; j++) {
                o[i][j] *= corr;
                sP[(ty * 4 + i) * 65 + tx * 4 + j] = p[j];
            }
        }
        __syncwarp();

#pragma unroll 8
        for (int k = 0; k < 64; k++) {
            float4 vv = *(float4*)&sV[k * 64 + tx * 4];
#pragma unroll
            for (int i = 0; i < 4; i++) {
                float pa = sP[(ty * 4 + i) * 65 + k];
                o[i][0] += pa * vv.x;
                o[i][1] += pa * vv.y;
                o[i][2] += pa * vv.z;
                o[i][3] += pa * vv.w;
            }
        }
        __syncwarp();
    }

#pragma unroll
    for (int i = 0; i < 4; i++) {
        float inv = 1.0f / l_i[i];
        int row = s0 + ty * 4 + i;
        float4 r4;
        r4.x = o[i][0] * inv; r4.y = o[i][1] * inv;
        r4.z = o[i][2] * inv; r4.w = o[i][3] * inv;
        *(float4*)&OUT[((size_t)b_ * Ss + row) * DM + h_ * HD + tx * 4] = r4;
    }
}

// ---------------------------------------------------------------------------
extern "C" void kernel_launch(void* const* d_in, const int* in_sizes, int n_in,
                              void* d_out, int out_size)
{
    const float* queries = (const float*)d_in[0];
    const float* keys    = (const float*)d_in[1];
    const float* values  = (const float*)d_in[2];
    // d_in[3] = mask (causal triu) — computed arithmetically instead
    const float* Wq = (const float*)d_in[4];
    const float* bq = (const float*)d_in[5];
    const float* Wk = (const float*)d_in[6];
    const float* bk = (const float*)d_in[7];
    const float* Wv = (const float*)d_in[8];
    const float* bv = (const float*)d_in[9];
    const float* Wo = (const float*)d_in[10];
    const float* bo = (const float*)d_in[11];

    // One-time host setup: cache scratch pointers + smem attributes.
    // (Caches pointers only — every call enqueues identical work.)
    static float *qs = nullptr, *ks = nullptr, *vs = nullptr, *att = nullptr;
    static __nv_bfloat16 *ahi, *alo, *bhi, *blo;
    if (qs == nullptr) {
        cudaGetSymbolAddress((void**)&qs,  g_Q);
        cudaGetSymbolAddress((void**)&ks,  g_K);
        cudaGetSymbolAddress((void**)&vs,  g_V);
        cudaGetSymbolAddress((void**)&att, g_att);
        cudaGetSymbolAddress((void**)&ahi, g_Ahi);
        cudaGetSymbolAddress((void**)&alo, g_Alo);
        cudaGetSymbolAddress((void**)&bhi, g_Bhi);
        cudaGetSymbolAddress((void**)&blo, g_Blo);
        cudaFuncSetAttribute(flash_kernel,
                             cudaFuncAttributeMaxDynamicSharedMemorySize,
                             FLASH_SMEM_BYTES);
        cudaFuncSetAttribute(gemm_mma<0>,
                             cudaFuncAttributeMaxDynamicSharedMemorySize,
                             G_SMEM_TOTAL);
        cudaFuncSetAttribute(gemm_mma<1>,
                             cudaFuncAttributeMaxDynamicSharedMemorySize,
                             G_SMEM_TOTAL);
    }

    const int n4 = NROWS * DM / 4;                 // conv_split float4 count
    dim3 cgrid((n4 + 255) / 256);
    dim3 wgrid(DM / 32, DM / 32), wblk(32, 8);
    dim3 ggrid(DM / 128, NROWS / 128);             // (8, 32)

    // Q projection
    conv_w_t<<<wgrid, wblk>>>(Wq, bhi, blo);
    conv_split<<<cgrid, 256>>>(queries, ahi, alo, n4);
    gemm_mma<1><<<ggrid, 256, G_SMEM_TOTAL>>>(ahi, alo, bhi, blo, bq, qs);
    // K projection
    conv_w_t<<<wgrid, wblk>>>(Wk, bhi, blo);
    conv_split<<<cgrid, 256>>>(keys, ahi, alo, n4);
    gemm_mma<1><<<ggrid, 256, G_SMEM_TOTAL>>>(ahi, alo, bhi, blo, bk, ks);
    // V projection
    conv_w_t<<<wgrid, wblk>>>(Wv, bhi, blo);
    conv_split<<<cgrid, 256>>>(values, ahi, alo, n4);
    gemm_mma<1><<<ggrid, 256, G_SMEM_TOTAL>>>(ahi, alo, bhi, blo, bv, vs);

    // Attention
    flash_kernel<<<dim3(Ss / 64, Bb * Hh), 256, FLASH_SMEM_BYTES>>>(qs, ks, vs, att);

    // Output projection
    conv_w_t<<<wgrid, wblk>>>(Wo, bhi, blo);
    conv_split<<<cgrid, 256>>>(att, ahi, alo, n4);
    gemm_mma<0><<<ggrid, 256, G_SMEM_TOTAL>>>(ahi, alo, bhi, blo, bo, (float*)d_out);
}

// round 13
// speedup vs baseline: 2.5455x; 1.8013x over previous
#include <cuda_runtime.h>
#include <cuda_bf16.h>
#include <cstdint>

#define Bb 2
#define Ss 2048
#define DM 1024
#define Hh 16
#define HD 64
#define NROWS (Bb*Ss)

// ---------------------------------------------------------------------------
// Scratch (device globals — no allocations allowed)
// ---------------------------------------------------------------------------
__device__ float g_Q[Bb*Hh*Ss*HD];          // [B,H,S,64]
__device__ float g_K[Bb*Hh*Ss*HD];
__device__ float g_V[Bb*Hh*Ss*HD];
__device__ float g_att[NROWS*DM];           // attention output, [B,S, H*64]
__device__ __nv_bfloat16 g_Ahi[NROWS*DM];   // split activations (reused per GEMM)
__device__ __nv_bfloat16 g_Alo[NROWS*DM];
__device__ __nv_bfloat16 g_Bhi[DM*DM];      // split+transposed weights [n][k]
__device__ __nv_bfloat16 g_Blo[DM*DM];

// Single dynamic-smem symbol shared by all kernels (type must agree TU-wide)
extern __shared__ char dyn_smem[];

// ---------------------------------------------------------------------------
// Helpers
// ---------------------------------------------------------------------------
__device__ __forceinline__ uint32_t smem_to_u32(const void* p) {
    uint32_t a;
    asm("{ .reg .u64 t; cvta.to.shared.u64 t, %1; cvt.u32.u64 %0, t; }"
        : "=r"(a) : "l"(p));
    return a;
}
__device__ __forceinline__ uint32_t swz128(uint32_t o) {
    return o ^ ((o >> 3) & 0x70);
}
__device__ __forceinline__ void ldsm4(uint32_t* r, uint32_t addr) {
    asm volatile("ldmatrix.sync.aligned.m8n8.x4.shared.b16 {%0,%1,%2,%3}, [%4];"
                 : "=r"(r[0]), "=r"(r[1]), "=r"(r[2]), "=r"(r[3]) : "r"(addr));
}
__device__ __forceinline__ void ldsm4t(uint32_t* r, uint32_t addr) {
    asm volatile("ldmatrix.sync.aligned.m8n8.x4.trans.shared.b16 {%0,%1,%2,%3}, [%4];"
                 : "=r"(r[0]), "=r"(r[1]), "=r"(r[2]), "=r"(r[3]) : "r"(addr));
}
// D (+)= A(m16k16,row) * B(k16n8,col) ; bf16 in, fp32 accum
__device__ __forceinline__ void mma_bf16(float* d, const uint32_t* a,
                                         const uint32_t b0, const uint32_t b1) {
    asm volatile(
        "mma.sync.aligned.m16n8k16.row.col.f32.bf16.bf16.f32 "
        "{%0,%1,%2,%3}, {%4,%5,%6,%7}, {%8,%9}, {%0,%1,%2,%3};"
        : "+f"(d[0]), "+f"(d[1]), "+f"(d[2]), "+f"(d[3])
        : "r"(a[0]), "r"(a[1]), "r"(a[2]), "r"(a[3]), "r"(b0), "r"(b1));
}
// split two fp32 into packed bf16x2 hi + residual lo (f0 in low half)
__device__ __forceinline__ void split2(float f0, float f1, uint32_t& hi, uint32_t& lo) {
    __nv_bfloat162 h = __floats2bfloat162_rn(f0, f1);
    float r0 = f0 - __bfloat162float(__low2bfloat16(h));
    float r1 = f1 - __bfloat162float(__high2bfloat16(h));
    __nv_bfloat162 l = __floats2bfloat162_rn(r0, r1);
    hi = *(uint32_t*)&h; lo = *(uint32_t*)&l;
}

// ---------------------------------------------------------------------------
// Conversion kernels: fp32 -> bf16 hi/lo split
// ---------------------------------------------------------------------------
__global__ __launch_bounds__(256) void conv_split(
    const float* __restrict__ X, __nv_bfloat16* __restrict__ Hi,
    __nv_bfloat16* __restrict__ Lo, int n4)
{
    int i = blockIdx.x * 256 + threadIdx.x;
    if (i >= n4) return;
    float4 v = ((const float4*)X)[i];
    uint2 hu, lu;
    split2(v.x, v.y, hu.x, lu.x);
    split2(v.z, v.w, hu.y, lu.y);
    *(uint2*)(Hi + 4 * (size_t)i) = hu;
    *(uint2*)(Lo + 4 * (size_t)i) = lu;
}

// W[k][n] fp32 -> out[n][k] bf16 hi/lo (transpose + split)
__global__ __launch_bounds__(256) void conv_w_t(
    const float* __restrict__ W, __nv_bfloat16* __restrict__ Hi,
    __nv_bfloat16* __restrict__ Lo)
{
    __shared__ float t[32][33];
    const int tx = threadIdx.x, ty = threadIdx.y;           // 32 x 8
    const int n0 = blockIdx.x * 32, k0 = blockIdx.y * 32;
#pragma unroll
    for (int r = ty; r < 32; r += 8)
        t[r][tx] = W[(size_t)(k0 + r) * DM + n0 + tx];
    __syncthreads();
#pragma unroll
    for (int r = ty; r < 32; r += 8) {
        float v = t[tx][r];                                  // W[k0+tx][n0+r]
        __nv_bfloat16 h = __float2bfloat16(v);
        __nv_bfloat16 l = __float2bfloat16(v - __bfloat162float(h));
        size_t o = (size_t)(n0 + r) * DM + k0 + tx;
        Hi[o] = h; Lo[o] = l;
    }
}

// ---------------------------------------------------------------------------
// mma.sync GEMM (unchanged — passing at ~70us each)
// ---------------------------------------------------------------------------
#define G_SMEM_TOTAL 65536   // 4 x 16KB: Ahi, Alo, Bhi, Blo (128 rows x 128B)

template <int MODE>
__global__ __launch_bounds__(256, 1) void gemm_mma(
    const __nv_bfloat16* __restrict__ Ahi, const __nv_bfloat16* __restrict__ Alo,
    const __nv_bfloat16* __restrict__ Bhi, const __nv_bfloat16* __restrict__ Blo,
    const float* __restrict__ bias, float* __restrict__ C)
{
    char* smem = dyn_smem;
    const uint32_t sb = smem_to_u32(smem);
    const int tid = threadIdx.x;
    const int lane = tid & 31, wid = tid >> 5;
    const int wm = (wid >> 1) * 32;          // warp m offset: 0,32,64,96
    const int wn = (wid & 1) * 64;           // warp n offset: 0,64
    const int n0 = blockIdx.x * 128, m0 = blockIdx.y * 128;

    float acc[2][8][4];
#pragma unroll
    for (int mt = 0; mt < 2; mt++)
#pragma unroll
        for (int nt = 0; nt < 8; nt++)
#pragma unroll
            for (int c = 0; c < 4; c++) acc[mt][nt][c] = 0.f;

    const int lr = lane & 15;                 // ldmatrix row within 16
    const int lc = (lane >> 4) * 16;          // ldmatrix 16B col select

    for (int ch = 0; ch < DM / 64; ch++) {
        __syncthreads();
        {
            const uint4* srcs[4] = {
                (const uint4*)Ahi + (size_t)m0 * 128 + ch * 8,
                (const uint4*)Alo + (size_t)m0 * 128 + ch * 8,
                (const uint4*)Bhi + (size_t)n0 * 128 + ch * 8,
                (const uint4*)Blo + (size_t)n0 * 128 + ch * 8 };
#pragma unroll
            for (int bf = 0; bf < 4; bf++) {
                const uint4* src = srcs[bf];
                char* dst = smem + bf * 16384;
#pragma unroll
                for (int it = 0; it < 4; it++) {
                    int t = tid + it * 256;       // 0..1023
                    int r = t >> 3, c = t & 7;
                    uint4 v = src[(size_t)r * 128 + c];
                    *(uint4*)(dst + swz128(r * 128 + c * 16)) = v;
                }
            }
        }
        __syncthreads();

#pragma unroll
        for (int kk = 0; kk < 4; kk++) {
            uint32_t ah[2][4], al[2][4], bh[8][2], bl[8][2];
#pragma unroll
            for (int mt = 0; mt < 2; mt++) {
                uint32_t off = (uint32_t)(wm + mt * 16 + lr) * 128 + kk * 32 + lc;
                uint32_t so = swz128(off);
                ldsm4(ah[mt], sb + so);
                ldsm4(al[mt], sb + 16384 + so);
            }
#pragma unroll
            for (int g = 0; g < 4; g++) {
                uint32_t off = (uint32_t)(wn + g * 16 + lr) * 128 + kk * 32 + lc;
                uint32_t so = swz128(off);
                uint32_t t4[4];
                ldsm4(t4, sb + 32768 + so);
                bh[2*g][0] = t4[0]; bh[2*g][1] = t4[2];
                bh[2*g+1][0] = t4[1]; bh[2*g+1][1] = t4[3];
                ldsm4(t4, sb + 49152 + so);
                bl[2*g][0] = t4[0]; bl[2*g][1] = t4[2];
                bl[2*g+1][0] = t4[1]; bl[2*g+1][1] = t4[3];
            }
#pragma unroll
            for (int mt = 0; mt < 2; mt++)
#pragma unroll
                for (int nt = 0; nt < 8; nt++) {
                    mma_bf16(acc[mt][nt], ah[mt], bh[nt][0], bh[nt][1]);
                    mma_bf16(acc[mt][nt], ah[mt], bl[nt][0], bl[nt][1]);
                    mma_bf16(acc[mt][nt], al[mt], bh[nt][0], bh[nt][1]);
                }
        }
    }

#pragma unroll
    for (int mt = 0; mt < 2; mt++) {
#pragma unroll
        for (int half = 0; half < 2; half++) {
            int m = m0 + wm + mt * 16 + (lane >> 2) + half * 8;
            int b_ = m / Ss, s_ = m - b_ * Ss;
#pragma unroll
            for (int nt = 0; nt < 8; nt++) {
                int n = n0 + wn + nt * 8 + (lane & 3) * 2;
                float v0 = acc[mt][nt][half * 2 + 0] + bias[n];
                float v1 = acc[mt][nt][half * 2 + 1] + bias[n + 1];
                if (MODE == 0) {
                    C[(size_t)m * DM + n]     = v0;
                    C[(size_t)m * DM + n + 1] = v1;
                } else {
                    int h = n >> 6, d = n & 63;
                    size_t base = (((size_t)b_ * Hh + h) * Ss + s_) * HD + d;
                    C[base]     = v0;
                    C[base + 1] = v1;
                }
            }
        }
    }
}

// ---------------------------------------------------------------------------
// Flash attention (causal) with split-bf16 mma.sync.
// CTA: 128 q-rows x (b,h); 256 threads / 8 warps; warp w owns S rows w*16..+16.
// Smem: Qhi/Qlo [128r x 128B] @0/16384; Khi/Klo [64 x 128B] @32768/40960;
//       Vhi/Vlo [64 x 128B] @49152/57344.  Total 64KB.
// Q scaled by 1/32 at fill (exact). P frags built from S accumulator registers.
// V consumed via ldmatrix.trans (stored key-major [k][d]).
// ---------------------------------------------------------------------------
#define FM_SMEM_BYTES 65536

__global__ __launch_bounds__(256) void flash_mma(
    const float* __restrict__ Q, const float* __restrict__ K,
    const float* __restrict__ V, float* __restrict__ OUT)
{
    char* smem = dyn_smem;
    const uint32_t sb = smem_to_u32(smem);
    const int tid = threadIdx.x, lane = tid & 31, w = tid >> 5;
    const int qi = (int)gridDim.x - 1 - (int)blockIdx.x;   // heavy tiles first
    const int bh = blockIdx.y;
    const int b_ = bh / Hh, h_ = bh & (Hh - 1);
    const int s0 = qi * 128;
    const int lr = lane & 15, lc = (lane >> 4) * 16;

    const uint32_t sQhi = sb,        sQlo = sb + 16384;
    const uint32_t sKhi = sb + 32768, sKlo = sb + 40960;
    const uint32_t sVhi = sb + 49152, sVlo = sb + 57344;

    // load + split Q (pre-scaled by 1/sqrt(1024) = 1/32, exact power of 2)
    {
        const float* Qb = Q + ((size_t)bh * Ss + s0) * HD;
#pragma unroll
        for (int it = 0; it < 8; it++) {
            int idx = tid + it * 256;           // 0..2047
            int r = idx >> 4, c = (idx & 15) * 4;
            float4 v = *(const float4*)&Qb[r * HD + c];
            uint2 h, l;
            split2(v.x * 0.03125f, v.y * 0.03125f, h.x, l.x);
            split2(v.z * 0.03125f, v.w * 0.03125f, h.y, l.y);
            uint32_t off = swz128((uint32_t)(r * 128 + c * 2));
            *(uint2*)(smem + off) = h;
            *(uint2*)(smem + 16384 + off) = l;
        }
    }

    float m0 = -1e30f, m1 = -1e30f, l0 = 0.f, l1 = 0.f;
    float o[8][4];
#pragma unroll
    for (int nt = 0; nt < 8; nt++)
#pragma unroll
        for (int c = 0; c < 4; c++) o[nt][c] = 0.f;

    const int row0 = s0 + w * 16 + (lane >> 2);
    const int nkt = 2 * qi + 2;

    for (int kt = 0; kt < nkt; kt++) {
        __syncthreads();
        // load + split K, V tiles (64 x 64 fp32 each)
        {
            const float* Kb = K + ((size_t)bh * Ss + kt * 64) * HD;
            const float* Vb = V + ((size_t)bh * Ss + kt * 64) * HD;
#pragma unroll
            for (int it = 0; it < 4; it++) {
                int idx = tid + it * 256;       // 0..1023
                int r = idx >> 4, c = (idx & 15) * 4;
                uint32_t off = swz128((uint32_t)(r * 128 + c * 2));
                float4 v = *(const float4*)&Kb[r * HD + c];
                uint2 h, l;
                split2(v.x, v.y, h.x, l.x);
                split2(v.z, v.w, h.y, l.y);
                *(uint2*)(smem + 32768 + off) = h;
                *(uint2*)(smem + 40960 + off) = l;
                v = *(const float4*)&Vb[r * HD + c];
                split2(v.x, v.y, h.x, l.x);
                split2(v.z, v.w, h.y, l.y);
                *(uint2*)(smem + 49152 + off) = h;
                *(uint2*)(smem + 57344 + off) = l;
            }
        }
        __syncthreads();

        // ---- S = Q K^T (warp: 16 rows x 64 cols), split 3-term ----
        float sa[8][4];
#pragma unroll
        for (int nt = 0; nt < 8; nt++)
#pragma unroll
            for (int c = 0; c < 4; c++) sa[nt][c] = 0.f;

#pragma unroll
        for (int kk = 0; kk < 4; kk++) {
            uint32_t ah[4], al[4];
            uint32_t aoff = swz128((uint32_t)((w * 16 + lr) * 128 + kk * 32 + lc));
            ldsm4(ah, sQhi + aoff);
            ldsm4(al, sQlo + aoff);
#pragma unroll
            for (int g = 0; g < 4; g++) {
                uint32_t koff = swz128((uint32_t)((g * 16 + lr) * 128 + kk * 32 + lc));
                uint32_t th[4], tl[4];
                ldsm4(th, sKhi + koff);
                ldsm4(tl, sKlo + koff);
                mma_bf16(sa[2*g],   ah, th[0], th[2]);
                mma_bf16(sa[2*g],   ah, tl[0], tl[2]);
                mma_bf16(sa[2*g],   al, th[0], th[2]);
                mma_bf16(sa[2*g+1], ah, th[1], th[3]);
                mma_bf16(sa[2*g+1], ah, tl[1], tl[3]);
                mma_bf16(sa[2*g+1], al, th[1], th[3]);
            }
        }

        // ---- causal mask (only last two k-tiles can cross the diagonal) ----
        if (kt >= 2 * qi) {
#pragma unroll
            for (int nt = 0; nt < 8; nt++) {
                int colb = kt * 64 + nt * 8 + (lane & 3) * 2;
                if (colb     > row0)     sa[nt][0] = -1e9f;
                if (colb + 1 > row0)     sa[nt][1] = -1e9f;
                if (colb     > row0 + 8) sa[nt][2] = -1e9f;
                if (colb + 1 > row0 + 8) sa[nt][3] = -1e9f;
            }
        }

        // ---- online softmax (rows row0, row0+8; 4-lane reductions) ----
        float mx0 = -1e30f, mx1 = -1e30f;
#pragma unroll
        for (int nt = 0; nt < 8; nt++) {
            mx0 = fmaxf(mx0, fmaxf(sa[nt][0], sa[nt][1]));
            mx1 = fmaxf(mx1, fmaxf(sa[nt][2], sa[nt][3]));
        }
        mx0 = fmaxf(mx0, __shfl_xor_sync(0xffffffffu, mx0, 1));
        mx0 = fmaxf(mx0, __shfl_xor_sync(0xffffffffu, mx0, 2));
        mx1 = fmaxf(mx1, __shfl_xor_sync(0xffffffffu, mx1, 1));
        mx1 = fmaxf(mx1, __shfl_xor_sync(0xffffffffu, mx1, 2));
        float mn0 = fmaxf(m0, mx0), mn1 = fmaxf(m1, mx1);
        float c0 = __expf(m0 - mn0), c1 = __expf(m1 - mn1);
        float rs0 = 0.f, rs1 = 0.f;
#pragma unroll
        for (int nt = 0; nt < 8; nt++) {
            sa[nt][0] = __expf(sa[nt][0] - mn0); rs0 += sa[nt][0];
            sa[nt][1] = __expf(sa[nt][1] - mn0); rs0 += sa[nt][1];
            sa[nt][2] = __expf(sa[nt][2] - mn1); rs1 += sa[nt][2];
            sa[nt][3] = __expf(sa[nt][3] - mn1); rs1 += sa[nt][3];
        }
        rs0 += __shfl_xor_sync(0xffffffffu, rs0, 1);
        rs0 += __shfl_xor_sync(0xffffffffu, rs0, 2);
        rs1 += __shfl_xor_sync(0xffffffffu, rs1, 1);
        rs1 += __shfl_xor_sync(0xffffffffu, rs1, 2);
        l0 = l0 * c0 + rs0; l1 = l1 * c1 + rs1;
        m0 = mn0; m1 = mn1;
#pragma unroll
        for (int nt = 0; nt < 8; nt++) {
            o[nt][0] *= c0; o[nt][1] *= c0;
            o[nt][2] *= c1; o[nt][3] *= c1;
        }

        // ---- O += P V  (P frags from registers; V via ldmatrix.trans) ----
#pragma unroll
        for (int k2 = 0; k2 < 4; k2++) {
            uint32_t phi[4], plo[4];
            split2(sa[2*k2][0],   sa[2*k2][1],   phi[0], plo[0]);
            split2(sa[2*k2][2],   sa[2*k2][3],   phi[1], plo[1]);
            split2(sa[2*k2+1][0], sa[2*k2+1][1], phi[2], plo[2]);
            split2(sa[2*k2+1][2], sa[2*k2+1][3], phi[3], plo[3]);
#pragma unroll
            for (int u = 0; u < 4; u++) {
                uint32_t voff = swz128((uint32_t)((k2 * 16 + lr) * 128 + u * 32 + lc));
                uint32_t th[4], tl[4];
                ldsm4t(th, sVhi + voff);
                ldsm4t(tl, sVlo + voff);
                mma_bf16(o[2*u],   phi, th[0], th[1]);
                mma_bf16(o[2*u],   phi, tl[0], tl[1]);
                mma_bf16(o[2*u],   plo, th[0], th[1]);
                mma_bf16(o[2*u+1], phi, th[2], th[3]);
                mma_bf16(o[2*u+1], phi, tl[2], tl[3]);
                mma_bf16(o[2*u+1], plo, th[2], th[3]);
            }
        }
    }

    // ---- epilogue: normalize, write [B,S, h*64+d] ----
    float i0 = 1.f / l0, i1 = 1.f / l1;
    float* O0 = OUT + ((size_t)b_ * Ss + row0) * DM + h_ * HD;
    float* O1 = O0 + 8 * DM;
#pragma unroll
    for (int nt = 0; nt < 8; nt++) {
        int d = nt * 8 + (lane & 3) * 2;
        float2 a; a.x = o[nt][0] * i0; a.y = o[nt][1] * i0;
        float2 b; b.x = o[nt][2] * i1; b.y = o[nt][3] * i1;
        *(float2*)(O0 + d) = a;
        *(float2*)(O1 + d) = b;
    }
}

// ---------------------------------------------------------------------------
extern "C" void kernel_launch(void* const* d_in, const int* in_sizes, int n_in,
                              void* d_out, int out_size)
{
    const float* queries = (const float*)d_in[0];
    const float* keys    = (const float*)d_in[1];
    const float* values  = (const float*)d_in[2];
    // d_in[3] = mask (causal triu) — computed arithmetically instead
    const float* Wq = (const float*)d_in[4];
    const float* bq = (const float*)d_in[5];
    const float* Wk = (const float*)d_in[6];
    const float* bk = (const float*)d_in[7];
    const float* Wv = (const float*)d_in[8];
    const float* bv = (const float*)d_in[9];
    const float* Wo = (const float*)d_in[10];
    const float* bo = (const float*)d_in[11];

    // One-time host setup: cache scratch pointers + smem attributes.
    // (Caches pointers only — every call enqueues identical work.)
    static float *qs = nullptr, *ks = nullptr, *vs = nullptr, *att = nullptr;
    static __nv_bfloat16 *ahi, *alo, *bhi, *blo;
    if (qs == nullptr) {
        cudaGetSymbolAddress((void**)&qs,  g_Q);
        cudaGetSymbolAddress((void**)&ks,  g_K);
        cudaGetSymbolAddress((void**)&vs,  g_V);
        cudaGetSymbolAddress((void**)&att, g_att);
        cudaGetSymbolAddress((void**)&ahi, g_Ahi);
        cudaGetSymbolAddress((void**)&alo, g_Alo);
        cudaGetSymbolAddress((void**)&bhi, g_Bhi);
        cudaGetSymbolAddress((void**)&blo, g_Blo);
        cudaFuncSetAttribute(flash_mma,
                             cudaFuncAttributeMaxDynamicSharedMemorySize,
                             FM_SMEM_BYTES);
        cudaFuncSetAttribute(gemm_mma<0>,
                             cudaFuncAttributeMaxDynamicSharedMemorySize,
                             G_SMEM_TOTAL);
        cudaFuncSetAttribute(gemm_mma<1>,
                             cudaFuncAttributeMaxDynamicSharedMemorySize,
                             G_SMEM_TOTAL);
    }

    const int n4 = NROWS * DM / 4;                 // conv_split float4 count
    dim3 cgrid((n4 + 255) / 256);
    dim3 wgrid(DM / 32, DM / 32), wblk(32, 8);
    dim3 ggrid(DM / 128, NROWS / 128);             // (8, 32)

    // Q projection
    conv_w_t<<<wgrid, wblk>>>(Wq, bhi, blo);
    conv_split<<<cgrid, 256>>>(queries, ahi, alo, n4);
    gemm_mma<1><<<ggrid, 256, G_SMEM_TOTAL>>>(ahi, alo, bhi, blo, bq, qs);
    // K projection
    conv_w_t<<<wgrid, wblk>>>(Wk, bhi, blo);
    conv_split<<<cgrid, 256>>>(keys, ahi, alo, n4);
    gemm_mma<1><<<ggrid, 256, G_SMEM_TOTAL>>>(ahi, alo, bhi, blo, bk, ks);
    // V projection
    conv_w_t<<<wgrid, wblk>>>(Wv, bhi, blo);
    conv_split<<<cgrid, 256>>>(values, ahi, alo, n4);
    gemm_mma<1><<<ggrid, 256, G_SMEM_TOTAL>>>(ahi, alo, bhi, blo, bv, vs);

    // Attention (split-bf16 tensor-core flash)
    flash_mma<<<dim3(Ss / 128, Bb * Hh), 256, FM_SMEM_BYTES>>>(qs, ks, vs, att);

    // Output projection
    conv_w_t<<<wgrid, wblk>>>(Wo, bhi, blo);
    conv_split<<<cgrid, 256>>>(att, ahi, alo, n4);
    gemm_mma<0><<<ggrid, 256, G_SMEM_TOTAL>>>(ahi, alo, bhi, blo, bo, (float*)d_out);
}

// round 15
// speedup vs baseline: 2.6345x; 1.0350x over previous
#include <cuda_runtime.h>
#include <cuda_bf16.h>
#include <cstdint>

#define Bb 2
#define Ss 2048
#define DM 1024
#define Hh 16
#define HD 64
#define NROWS (Bb*Ss)

// ---------------------------------------------------------------------------
// Scratch (device globals — no allocations allowed)
// Projections are stored PRE-SPLIT as bf16 hi/lo pairs, [B,H,S,64].
// ---------------------------------------------------------------------------
__device__ __nv_bfloat16 g_Qhi[Bb*Hh*Ss*HD], g_Qlo[Bb*Hh*Ss*HD];
__device__ __nv_bfloat16 g_Khi[Bb*Hh*Ss*HD], g_Klo[Bb*Hh*Ss*HD];
__device__ __nv_bfloat16 g_Vhi[Bb*Hh*Ss*HD], g_Vlo[Bb*Hh*Ss*HD];
__device__ float g_att[NROWS*DM];           // attention output, [B,S, H*64]
__device__ __nv_bfloat16 g_Bhi[DM*DM];      // split+transposed weights [n][k]
__device__ __nv_bfloat16 g_Blo[DM*DM];

// Single dynamic-smem symbol shared by all kernels (type must agree TU-wide)
extern __shared__ char dyn_smem[];

// ---------------------------------------------------------------------------
// Helpers
// ---------------------------------------------------------------------------
__device__ __forceinline__ uint32_t smem_to_u32(const void* p) {
    uint32_t a;
    asm("{ .reg .u64 t; cvta.to.shared.u64 t, %1; cvt.u32.u64 %0, t; }"
        : "=r"(a) : "l"(p));
    return a;
}
__device__ __forceinline__ uint32_t swz128(uint32_t o) {
    return o ^ ((o >> 3) & 0x70);
}
__device__ __forceinline__ void ldsm4(uint32_t* r, uint32_t addr) {
    asm volatile("ldmatrix.sync.aligned.m8n8.x4.shared.b16 {%0,%1,%2,%3}, [%4];"
                 : "=r"(r[0]), "=r"(r[1]), "=r"(r[2]), "=r"(r[3]) : "r"(addr));
}
__device__ __forceinline__ void ldsm4t(uint32_t* r, uint32_t addr) {
    asm volatile("ldmatrix.sync.aligned.m8n8.x4.trans.shared.b16 {%0,%1,%2,%3}, [%4];"
                 : "=r"(r[0]), "=r"(r[1]), "=r"(r[2]), "=r"(r[3]) : "r"(addr));
}
// D (+)= A(m16k16,row) * B(k16n8,col) ; bf16 in, fp32 accum
__device__ __forceinline__ void mma_bf16(float* d, const uint32_t* a,
                                         const uint32_t b0, const uint32_t b1) {
    asm volatile(
        "mma.sync.aligned.m16n8k16.row.col.f32.bf16.bf16.f32 "
        "{%0,%1,%2,%3}, {%4,%5,%6,%7}, {%8,%9}, {%0,%1,%2,%3};"
        : "+f"(d[0]), "+f"(d[1]), "+f"(d[2]), "+f"(d[3])
        : "r"(a[0]), "r"(a[1]), "r"(a[2]), "r"(a[3]), "r"(b0), "r"(b1));
}
// split two fp32 into packed bf16x2 hi + residual lo (f0 in low half)
__device__ __forceinline__ void split2(float f0, float f1, uint32_t& hi, uint32_t& lo) {
    __nv_bfloat162 h = __floats2bfloat162_rn(f0, f1);
    float r0 = f0 - __bfloat162float(__low2bfloat16(h));
    float r1 = f1 - __bfloat162float(__high2bfloat16(h));
    __nv_bfloat162 l = __floats2bfloat162_rn(r0, r1);
    hi = *(uint32_t*)&h; lo = *(uint32_t*)&l;
}
// cp.async 16B gmem -> smem
__device__ __forceinline__ void cpa16(uint32_t dst, const void* src) {
    asm volatile("cp.async.cg.shared.global [%0], [%1], 16;"
                 :: "r"(dst), "l"(src) : "memory");
}
__device__ __forceinline__ void cpa_commit() {
    asm volatile("cp.async.commit_group;" ::: "memory");
}
__device__ __forceinline__ void cpa_wait0() {
    asm volatile("cp.async.wait_group 0;" ::: "memory");
}

// ---------------------------------------------------------------------------
// W[k][n] fp32 -> out[n][k] bf16 hi/lo (transpose + split)
// ---------------------------------------------------------------------------
__global__ __launch_bounds__(256) void conv_w_t(
    const float* __restrict__ W, __nv_bfloat16* __restrict__ Hi,
    __nv_bfloat16* __restrict__ Lo)
{
    __shared__ float t[32][33];
    const int tx = threadIdx.x, ty = threadIdx.y;           // 32 x 8
    const int n0 = blockIdx.x * 32, k0 = blockIdx.y * 32;
#pragma unroll
    for (int r = ty; r < 32; r += 8)
        t[r][tx] = W[(size_t)(k0 + r) * DM + n0 + tx];
    __syncthreads();
#pragma unroll
    for (int r = ty; r < 32; r += 8) {
        float v = t[tx][r];                                  // W[k0+tx][n0+r]
        __nv_bfloat16 h = __float2bfloat16(v);
        __nv_bfloat16 l = __float2bfloat16(v - __bfloat162float(h));
        size_t o = (size_t)(n0 + r) * DM + k0 + tx;
        Hi[o] = h; Lo[o] = l;
    }
}

// ---------------------------------------------------------------------------
// mma.sync GEMM: C[m][n] = sum_k X[m][k]*W[k][n] + bias[n]
//   X fp32 row-major (split to bf16 hi/lo INLINE during smem fill).
//   B split bf16 [n][k] (= W^T) from conv_w_t, loaded via cp.async.
//   3-MMA split accumulation; CTA 128x128, K-chunk 64, 8 warps x (32x64).
// MODE 0: write fp32 C row-major [NROWS,DM].
// MODE 1: split accumulator and write bf16 Chi/Clo head-remapped [B,H,S,64].
// ---------------------------------------------------------------------------
#define G_SMEM_TOTAL 65536   // Ahi@0, Alo@16K, Bhi@32K, Blo@48K (16KB each)

template <int MODE>
__global__ __launch_bounds__(256, 1) void gemm_mma(
    const float* __restrict__ X,
    const __nv_bfloat16* __restrict__ Bhi, const __nv_bfloat16* __restrict__ Blo,
    const float* __restrict__ bias, float* __restrict__ C,
    __nv_bfloat16* __restrict__ Chi, __nv_bfloat16* __restrict__ Clo)
{
    char* smem = dyn_smem;
    const uint32_t sb = smem_to_u32(smem);
    const int tid = threadIdx.x;
    const int lane = tid & 31, wid = tid >> 5;
    const int wm = (wid >> 1) * 32;          // warp m offset: 0,32,64,96
    const int wn = (wid & 1) * 64;           // warp n offset: 0,64
    const int n0 = blockIdx.x * 128, m0 = blockIdx.y * 128;

    float acc[2][8][4];
#pragma unroll
    for (int mt = 0; mt < 2; mt++)
#pragma unroll
        for (int nt = 0; nt < 8; nt++)
#pragma unroll
            for (int c = 0; c < 4; c++) acc[mt][nt][c] = 0.f;

    const int lr = lane & 15;                 // ldmatrix row within 16
    const int lc = (lane >> 4) * 16;          // ldmatrix 16B col select

    for (int ch = 0; ch < DM / 64; ch++) {
        __syncthreads();
        // B tiles via cp.async (no transform needed)
#pragma unroll
        for (int it = 0; it < 4; it++) {
            int t = tid + it * 256;           // 0..1023
            int r = t >> 3, c = t & 7;
            uint32_t doff = swz128((uint32_t)(r * 128 + c * 16));
            const uint4* s0 = (const uint4*)Bhi + (size_t)(n0 + r) * 128 + ch * 8 + c;
            const uint4* s1 = (const uint4*)Blo + (size_t)(n0 + r) * 128 + ch * 8 + c;
            cpa16(sb + 32768 + doff, s0);
            cpa16(sb + 49152 + doff, s1);
        }
        cpa_commit();
        // A tile: fp32 load + inline split (overlaps with B cp.async)
#pragma unroll
        for (int it = 0; it < 8; it++) {
            int idx = tid + it * 256;         // 0..2047
            int r = idx >> 4, c4 = idx & 15;
            float4 v = ((const float4*)(X + (size_t)(m0 + r) * DM + ch * 64))[c4];
            uint2 h, l;
            split2(v.x, v.y, h.x, l.x);
            split2(v.z, v.w, h.y, l.y);
            uint32_t off = swz128((uint32_t)(r * 128 + c4 * 8));
            *(uint2*)(smem + off) = h;
            *(uint2*)(smem + 16384 + off) = l;
        }
        cpa_wait0();
        __syncthreads();

#pragma unroll
        for (int kk = 0; kk < 4; kk++) {
            uint32_t ah[2][4], al[2][4], bh[8][2], bl[8][2];
#pragma unroll
            for (int mt = 0; mt < 2; mt++) {
                uint32_t off = (uint32_t)(wm + mt * 16 + lr) * 128 + kk * 32 + lc;
                uint32_t so = swz128(off);
                ldsm4(ah[mt], sb + so);
                ldsm4(al[mt], sb + 16384 + so);
            }
#pragma unroll
            for (int g = 0; g < 4; g++) {
                uint32_t off = (uint32_t)(wn + g * 16 + lr) * 128 + kk * 32 + lc;
                uint32_t so = swz128(off);
                uint32_t t4[4];
                ldsm4(t4, sb + 32768 + so);
                bh[2*g][0] = t4[0]; bh[2*g][1] = t4[2];
                bh[2*g+1][0] = t4[1]; bh[2*g+1][1] = t4[3];
                ldsm4(t4, sb + 49152 + so);
                bl[2*g][0] = t4[0]; bl[2*g][1] = t4[2];
                bl[2*g+1][0] = t4[1]; bl[2*g+1][1] = t4[3];
            }
#pragma unroll
            for (int mt = 0; mt < 2; mt++)
#pragma unroll
                for (int nt = 0; nt < 8; nt++) {
                    mma_bf16(acc[mt][nt], ah[mt], bh[nt][0], bh[nt][1]);
                    mma_bf16(acc[mt][nt], ah[mt], bl[nt][0], bl[nt][1]);
                    mma_bf16(acc[mt][nt], al[mt], bh[nt][0], bh[nt][1]);
                }
        }
    }

#pragma unroll
    for (int mt = 0; mt < 2; mt++) {
#pragma unroll
        for (int half = 0; half < 2; half++) {
            int m = m0 + wm + mt * 16 + (lane >> 2) + half * 8;
            int b_ = m / Ss, s_ = m - b_ * Ss;
#pragma unroll
            for (int nt = 0; nt < 8; nt++) {
                int n = n0 + wn + nt * 8 + (lane & 3) * 2;
                float v0 = acc[mt][nt][half * 2 + 0] + bias[n];
                float v1 = acc[mt][nt][half * 2 + 1] + bias[n + 1];
                if (MODE == 0) {
                    C[(size_t)m * DM + n]     = v0;
                    C[(size_t)m * DM + n + 1] = v1;
                } else {
                    int h = n >> 6, d = n & 63;
                    size_t base = (((size_t)b_ * Hh + h) * Ss + s_) * HD + d;
                    uint32_t hi, lo;
                    split2(v0, v1, hi, lo);   // d even -> 4B-aligned pair
                    *(uint32_t*)(Chi + base) = hi;
                    *(uint32_t*)(Clo + base) = lo;
                }
            }
        }
    }
}

// ---------------------------------------------------------------------------
// Flash attention (causal), split-bf16 mma.sync, PRE-SPLIT inputs.
// CTA: 128 q-rows x (b,h); 256 threads / 8 warps; warp w owns S rows w*16..+16.
// Smem: Qhi/Qlo [128r x 128B] @0/16384; Khi/Klo @32768/40960;
//       Vhi/Vlo @49152/57344 (8KB each KV buf). Total 64KB.
// All tile loads are cp.async 16B copies — zero conversion ALU in mainloop.
// Q pre-scaled by 1/32? NO — scale now applied to scores via exp argument:
//   Q was NOT pre-scaled at projection time, so scale S by 0.03125 after MMA.
// ---------------------------------------------------------------------------
#define FM_SMEM_BYTES 65536

__global__ __launch_bounds__(256) void flash_mma(
    const __nv_bfloat16* __restrict__ Qhi, const __nv_bfloat16* __restrict__ Qlo,
    const __nv_bfloat16* __restrict__ Khi, const __nv_bfloat16* __restrict__ Klo,
    const __nv_bfloat16* __restrict__ Vhi, const __nv_bfloat16* __restrict__ Vlo,
    float* __restrict__ OUT)
{
    char* smem = dyn_smem;
    const uint32_t sb = smem_to_u32(smem);
    const int tid = threadIdx.x, lane = tid & 31, w = tid >> 5;
    const int qi = (int)gridDim.x - 1 - (int)blockIdx.x;   // heavy tiles first
    const int bh = blockIdx.y;
    const int b_ = bh / Hh, h_ = bh & (Hh - 1);
    const int s0 = qi * 128;
    const int lr = lane & 15, lc = (lane >> 4) * 16;

    const uint32_t sQhi = sb,         sQlo = sb + 16384;
    const uint32_t sKhi = sb + 32768, sKlo = sb + 40960;
    const uint32_t sVhi = sb + 49152, sVlo = sb + 57344;

    // Q tiles: straight cp.async copies (pre-split in gmem)
    {
        const uint4* q0 = (const uint4*)(Qhi + ((size_t)bh * Ss + s0) * HD);
        const uint4* q1 = (const uint4*)(Qlo + ((size_t)bh * Ss + s0) * HD);
#pragma unroll
        for (int it = 0; it < 4; it++) {
            int t = tid + it * 256;           // 0..1023
            int r = t >> 3, c = t & 7;
            uint32_t doff = swz128((uint32_t)(r * 128 + c * 16));
            cpa16(sQhi + doff, q0 + r * 8 + c);
            cpa16(sQlo + doff, q1 + r * 8 + c);
        }
        cpa_commit();
    }

    float m0 = -1e30f, m1 = -1e30f, l0 = 0.f, l1 = 0.f;
    float o[8][4];
#pragma unroll
    for (int nt = 0; nt < 8; nt++)
#pragma unroll
        for (int c = 0; c < 4; c++) o[nt][c] = 0.f;

    const int row0 = s0 + w * 16 + (lane >> 2);
    const int nkt = 2 * qi + 2;

    for (int kt = 0; kt < nkt; kt++) {
        __syncthreads();
        // K/V tiles via cp.async (4 x 8KB bufs)
        {
            const size_t roff = ((size_t)bh * Ss + kt * 64) * HD;
            const uint4* srcs[4] = {
                (const uint4*)(Khi + roff), (const uint4*)(Klo + roff),
                (const uint4*)(Vhi + roff), (const uint4*)(Vlo + roff) };
#pragma unroll
            for (int it = 0; it < 8; it++) {
                int idx = tid + it * 256;     // 0..2047
                int buf = idx >> 9;           // 0..3
                int j = idx & 511;
                int r = j >> 3, c = j & 7;
                uint32_t doff = swz128((uint32_t)(r * 128 + c * 16));
                cpa16(sKhi + buf * 8192 + doff, srcs[buf] + r * 8 + c);
            }
            cpa_commit();
        }
        cpa_wait0();
        __syncthreads();

        // ---- S = Q K^T (warp: 16 rows x 64 cols), split 3-term ----
        float sa[8][4];
#pragma unroll
        for (int nt = 0; nt < 8; nt++)
#pragma unroll
            for (int c = 0; c < 4; c++) sa[nt][c] = 0.f;

#pragma unroll
        for (int kk = 0; kk < 4; kk++) {
            uint32_t ah[4], al[4];
            uint32_t aoff = swz128((uint32_t)((w * 16 + lr) * 128 + kk * 32 + lc));
            ldsm4(ah, sQhi + aoff);
            ldsm4(al, sQlo + aoff);
#pragma unroll
            for (int g = 0; g < 4; g++) {
                uint32_t koff = swz128((uint32_t)((g * 16 + lr) * 128 + kk * 32 + lc));
                uint32_t th[4], tl[4];
                ldsm4(th, sKhi + koff);
                ldsm4(tl, sKlo + koff);
                mma_bf16(sa[2*g],   ah, th[0], th[2]);
                mma_bf16(sa[2*g],   ah, tl[0], tl[2]);
                mma_bf16(sa[2*g],   al, th[0], th[2]);
                mma_bf16(sa[2*g+1], ah, th[1], th[3]);
                mma_bf16(sa[2*g+1], ah, tl[1], tl[3]);
                mma_bf16(sa[2*g+1], al, th[1], th[3]);
            }
        }
        // scale by 1/sqrt(1024)
#pragma unroll
        for (int nt = 0; nt < 8; nt++)
#pragma unroll
            for (int c = 0; c < 4; c++) sa[nt][c] *= 0.03125f;

        // ---- causal mask (only last two k-tiles can cross the diagonal) ----
        if (kt >= 2 * qi) {
#pragma unroll
            for (int nt = 0; nt < 8; nt++) {
                int colb = kt * 64 + nt * 8 + (lane & 3) * 2;
                if (colb     > row0)     sa[nt][0] = -1e9f;
                if (colb + 1 > row0)     sa[nt][1] = -1e9f;
                if (colb     > row0 + 8) sa[nt][2] = -1e9f;
                if (colb + 1 > row0 + 8) sa[nt][3] = -1e9f;
            }
        }

        // ---- online softmax (rows row0, row0+8; 4-lane reductions) ----
        float mx0 = -1e30f, mx1 = -1e30f;
#pragma unroll
        for (int nt = 0; nt < 8; nt++) {
            mx0 = fmaxf(mx0, fmaxf(sa[nt][0], sa[nt][1]));
            mx1 = fmaxf(mx1, fmaxf(sa[nt][2], sa[nt][3]));
        }
        mx0 = fmaxf(mx0, __shfl_xor_sync(0xffffffffu, mx0, 1));
        mx0 = fmaxf(mx0, __shfl_xor_sync(0xffffffffu, mx0, 2));
        mx1 = fmaxf(mx1, __shfl_xor_sync(0xffffffffu, mx1, 1));
        mx1 = fmaxf(mx1, __shfl_xor_sync(0xffffffffu, mx1, 2));
        float mn0 = fmaxf(m0, mx0), mn1 = fmaxf(m1, mx1);
        float c0 = __expf(m0 - mn0), c1 = __expf(m1 - mn1);
        float rs0 = 0.f, rs1 = 0.f;
#pragma unroll
        for (int nt = 0; nt < 8; nt++) {
            sa[nt][0] = __expf(sa[nt][0] - mn0); rs0 += sa[nt][0];
            sa[nt][1] = __expf(sa[nt][1] - mn0); rs0 += sa[nt][1];
            sa[nt][2] = __expf(sa[nt][2] - mn1); rs1 += sa[nt][2];
            sa[nt][3] = __expf(sa[nt][3] - mn1); rs1 += sa[nt][3];
        }
        rs0 += __shfl_xor_sync(0xffffffffu, rs0, 1);
        rs0 += __shfl_xor_sync(0xffffffffu, rs0, 2);
        rs1 += __shfl_xor_sync(0xffffffffu, rs1, 1);
        rs1 += __shfl_xor_sync(0xffffffffu, rs1, 2);
        l0 = l0 * c0 + rs0; l1 = l1 * c1 + rs1;
        m0 = mn0; m1 = mn1;
#pragma unroll
        for (int nt = 0; nt < 8; nt++) {
            o[nt][0] *= c0; o[nt][1] *= c0;
            o[nt][2] *= c1; o[nt][3] *= c1;
        }

        // ---- O += P V  (P frags from registers; V via ldmatrix.trans) ----
#pragma unroll
        for (int k2 = 0; k2 < 4; k2++) {
            uint32_t phi[4], plo[4];
            split2(sa[2*k2][0],   sa[2*k2][1],   phi[0], plo[0]);
            split2(sa[2*k2][2],   sa[2*k2][3],   phi[1], plo[1]);
            split2(sa[2*k2+1][0], sa[2*k2+1][1], phi[2], plo[2]);
            split2(sa[2*k2+1][2], sa[2*k2+1][3], phi[3], plo[3]);
#pragma unroll
            for (int u = 0; u < 4; u++) {
                uint32_t voff = swz128((uint32_t)((k2 * 16 + lr) * 128 + u * 32 + lc));
                uint32_t th[4], tl[4];
                ldsm4t(th, sVhi + voff);
                ldsm4t(tl, sVlo + voff);
                mma_bf16(o[2*u],   phi, th[0], th[1]);
                mma_bf16(o[2*u],   phi, tl[0], tl[1]);
                mma_bf16(o[2*u],   plo, th[0], th[1]);
                mma_bf16(o[2*u+1], phi, th[2], th[3]);
                mma_bf16(o[2*u+1], phi, tl[2], tl[3]);
                mma_bf16(o[2*u+1], plo, th[2], th[3]);
            }
        }
    }

    // ---- epilogue: normalize, write [B,S, h*64+d] ----
    float i0 = 1.f / l0, i1 = 1.f / l1;
    float* O0 = OUT + ((size_t)b_ * Ss + row0) * DM + h_ * HD;
    float* O1 = O0 + 8 * DM;
#pragma unroll
    for (int nt = 0; nt < 8; nt++) {
        int d = nt * 8 + (lane & 3) * 2;
        float2 a; a.x = o[nt][0] * i0; a.y = o[nt][1] * i0;
        float2 b; b.x = o[nt][2] * i1; b.y = o[nt][3] * i1;
        *(float2*)(O0 + d) = a;
        *(float2*)(O1 + d) = b;
    }
}

// ---------------------------------------------------------------------------
extern "C" void kernel_launch(void* const* d_in, const int* in_sizes, int n_in,
                              void* d_out, int out_size)
{
    const float* queries = (const float*)d_in[0];
    const float* keys    = (const float*)d_in[1];
    const float* values  = (const float*)d_in[2];
    // d_in[3] = mask (causal triu) — computed arithmetically instead
    const float* Wq = (const float*)d_in[4];
    const float* bq = (const float*)d_in[5];
    const float* Wk = (const float*)d_in[6];
    const float* bk = (const float*)d_in[7];
    const float* Wv = (const float*)d_in[8];
    const float* bv = (const float*)d_in[9];
    const float* Wo = (const float*)d_in[10];
    const float* bo = (const float*)d_in[11];

    // One-time host setup: cache scratch pointers + smem attributes.
    // (Caches pointers only — every call enqueues identical work.)
    static float* att = nullptr;
    static __nv_bfloat16 *qhi, *qlo, *khi, *klo, *vhi, *vlo, *bhi, *blo;
    if (att == nullptr) {
        cudaGetSymbolAddress((void**)&qhi, g_Qhi);
        cudaGetSymbolAddress((void**)&qlo, g_Qlo);
        cudaGetSymbolAddress((void**)&khi, g_Khi);
        cudaGetSymbolAddress((void**)&klo, g_Klo);
        cudaGetSymbolAddress((void**)&vhi, g_Vhi);
        cudaGetSymbolAddress((void**)&vlo, g_Vlo);
        cudaGetSymbolAddress((void**)&att, g_att);
        cudaGetSymbolAddress((void**)&bhi, g_Bhi);
        cudaGetSymbolAddress((void**)&blo, g_Blo);
        cudaFuncSetAttribute(flash_mma,
                             cudaFuncAttributeMaxDynamicSharedMemorySize,
                             FM_SMEM_BYTES);
        cudaFuncSetAttribute(gemm_mma<0>,
                             cudaFuncAttributeMaxDynamicSharedMemorySize,
                             G_SMEM_TOTAL);
        cudaFuncSetAttribute(gemm_mma<1>,
                             cudaFuncAttributeMaxDynamicSharedMemorySize,
                             G_SMEM_TOTAL);
    }

    dim3 wgrid(DM / 32, DM / 32), wblk(32, 8);
    dim3 ggrid(DM / 128, NROWS / 128);             // (8, 32)

    // Q projection -> split bf16 [B,H,S,64]
    conv_w_t<<<wgrid, wblk>>>(Wq, bhi, blo);
    gemm_mma<1><<<ggrid, 256, G_SMEM_TOTAL>>>(queries, bhi, blo, bq,
                                              nullptr, qhi, qlo);
    // K projection
    conv_w_t<<<wgrid, wblk>>>(Wk, bhi, blo);
    gemm_mma<1><<<ggrid, 256, G_SMEM_TOTAL>>>(keys, bhi, blo, bk,
                                              nullptr, khi, klo);
    // V projection
    conv_w_t<<<wgrid, wblk>>>(Wv, bhi, blo);
    gemm_mma<1><<<ggrid, 256, G_SMEM_TOTAL>>>(values, bhi, blo, bv,
                                              nullptr, vhi, vlo);

    // Attention (split-bf16 tensor-core flash, pre-split inputs)
    flash_mma<<<dim3(Ss / 128, Bb * Hh), 256, FM_SMEM_BYTES>>>(
        qhi, qlo, khi, klo, vhi, vlo, att);

    // Output projection (fp32 att in, fp32 out)
    conv_w_t<<<wgrid, wblk>>>(Wo, bhi, blo);
    gemm_mma<0><<<ggrid, 256, G_SMEM_TOTAL>>>(att, bhi, blo, bo,
                                              (float*)d_out, nullptr, nullptr);
}

// round 16
// speedup vs baseline: 3.0144x; 1.1442x over previous
#include <cuda_runtime.h>
#include <cuda_bf16.h>
#include <cstdint>

#define Bb 2
#define Ss 2048
#define DM 1024
#define Hh 16
#define HD 64
#define NROWS (Bb*Ss)

// ---------------------------------------------------------------------------
// Scratch (device globals — no allocations allowed)
// Projections are stored PRE-SPLIT as bf16 hi/lo pairs, [B,H,S,64].
// ---------------------------------------------------------------------------
__device__ __nv_bfloat16 g_Qhi[Bb*Hh*Ss*HD], g_Qlo[Bb*Hh*Ss*HD];
__device__ __nv_bfloat16 g_Khi[Bb*Hh*Ss*HD], g_Klo[Bb*Hh*Ss*HD];
__device__ __nv_bfloat16 g_Vhi[Bb*Hh*Ss*HD], g_Vlo[Bb*Hh*Ss*HD];
__device__ float g_att[NROWS*DM];           // attention output, [B,S, H*64]
__device__ __nv_bfloat16 g_Bhi[DM*DM];      // split+transposed weights [n][k]
__device__ __nv_bfloat16 g_Blo[DM*DM];

// Single dynamic-smem symbol shared by all kernels (type must agree TU-wide)
extern __shared__ char dyn_smem[];

// ---------------------------------------------------------------------------
// Helpers
// ---------------------------------------------------------------------------
__device__ __forceinline__ uint32_t smem_to_u32(const void* p) {
    uint32_t a;
    asm("{ .reg .u64 t; cvta.to.shared.u64 t, %1; cvt.u32.u64 %0, t; }"
        : "=r"(a) : "l"(p));
    return a;
}
__device__ __forceinline__ uint32_t swz128(uint32_t o) {
    return o ^ ((o >> 3) & 0x70);
}
__device__ __forceinline__ void ldsm4(uint32_t* r, uint32_t addr) {
    asm volatile("ldmatrix.sync.aligned.m8n8.x4.shared.b16 {%0,%1,%2,%3}, [%4];"
                 : "=r"(r[0]), "=r"(r[1]), "=r"(r[2]), "=r"(r[3]) : "r"(addr));
}
__device__ __forceinline__ void ldsm4t(uint32_t* r, uint32_t addr) {
    asm volatile("ldmatrix.sync.aligned.m8n8.x4.trans.shared.b16 {%0,%1,%2,%3}, [%4];"
                 : "=r"(r[0]), "=r"(r[1]), "=r"(r[2]), "=r"(r[3]) : "r"(addr));
}
// D (+)= A(m16k16,row) * B(k16n8,col) ; bf16 in, fp32 accum
__device__ __forceinline__ void mma_bf16(float* d, const uint32_t* a,
                                         const uint32_t b0, const uint32_t b1) {
    asm volatile(
        "mma.sync.aligned.m16n8k16.row.col.f32.bf16.bf16.f32 "
        "{%0,%1,%2,%3}, {%4,%5,%6,%7}, {%8,%9}, {%0,%1,%2,%3};"
        : "+f"(d[0]), "+f"(d[1]), "+f"(d[2]), "+f"(d[3])
        : "r"(a[0]), "r"(a[1]), "r"(a[2]), "r"(a[3]), "r"(b0), "r"(b1));
}
// split two fp32 into packed bf16x2 hi + residual lo (f0 in low half)
__device__ __forceinline__ void split2(float f0, float f1, uint32_t& hi, uint32_t& lo) {
    __nv_bfloat162 h = __floats2bfloat162_rn(f0, f1);
    float r0 = f0 - __bfloat162float(__low2bfloat16(h));
    float r1 = f1 - __bfloat162float(__high2bfloat16(h));
    __nv_bfloat162 l = __floats2bfloat162_rn(r0, r1);
    hi = *(uint32_t*)&h; lo = *(uint32_t*)&l;
}
// cp.async 16B gmem -> smem
__device__ __forceinline__ void cpa16(uint32_t dst, const void* src) {
    asm volatile("cp.async.cg.shared.global [%0], [%1], 16;"
                 :: "r"(dst), "l"(src) : "memory");
}
__device__ __forceinline__ void cpa_commit() {
    asm volatile("cp.async.commit_group;" ::: "memory");
}
__device__ __forceinline__ void cpa_wait0() {
    asm volatile("cp.async.wait_group 0;" ::: "memory");
}
__device__ __forceinline__ void cpa_wait1() {
    asm volatile("cp.async.wait_group 1;" ::: "memory");
}

// ---------------------------------------------------------------------------
// W[k][n] fp32 -> out[n][k] bf16 hi/lo (transpose + split)
// ---------------------------------------------------------------------------
__global__ __launch_bounds__(256) void conv_w_t(
    const float* __restrict__ W, __nv_bfloat16* __restrict__ Hi,
    __nv_bfloat16* __restrict__ Lo)
{
    __shared__ float t[32][33];
    const int tx = threadIdx.x, ty = threadIdx.y;           // 32 x 8
    const int n0 = blockIdx.x * 32, k0 = blockIdx.y * 32;
#pragma unroll
    for (int r = ty; r < 32; r += 8)
        t[r][tx] = W[(size_t)(k0 + r) * DM + n0 + tx];
    __syncthreads();
#pragma unroll
    for (int r = ty; r < 32; r += 8) {
        float v = t[tx][r];                                  // W[k0+tx][n0+r]
        __nv_bfloat16 h = __float2bfloat16(v);
        __nv_bfloat16 l = __float2bfloat16(v - __bfloat162float(h));
        size_t o = (size_t)(n0 + r) * DM + k0 + tx;
        Hi[o] = h; Lo[o] = l;
    }
}

// ---------------------------------------------------------------------------
// mma.sync GEMM, DOUBLE-BUFFERED: C[m][n] = sum_k X[m][k]*W[k][n] + bias[n]
//   X fp32 row-major (prefetched to regs during MMA, split+STS after).
//   B split bf16 [n][k] via cp.async.  2 smem stages x 64KB = 128KB.
// MODE 0: write fp32 C row-major.  MODE 1: split bf16 Chi/Clo [B,H,S,64].
// ---------------------------------------------------------------------------
#define G_SMEM_TOTAL 131072   // stage s at s*65536: Ahi@0 Alo@16K Bhi@32K Blo@48K
#define GK_NCH (DM / 64)      // 16

template <int MODE>
__global__ __launch_bounds__(256, 1) void gemm_mma(
    const float* __restrict__ X,
    const __nv_bfloat16* __restrict__ Bhi, const __nv_bfloat16* __restrict__ Blo,
    const float* __restrict__ bias, float* __restrict__ C,
    __nv_bfloat16* __restrict__ Chi, __nv_bfloat16* __restrict__ Clo)
{
    char* smem = dyn_smem;
    const uint32_t sb = smem_to_u32(smem);
    const int tid = threadIdx.x;
    const int lane = tid & 31, wid = tid >> 5;
    const int wm = (wid >> 1) * 32;          // warp m offset: 0,32,64,96
    const int wn = (wid & 1) * 64;           // warp n offset: 0,64
    const int n0 = blockIdx.x * 128, m0 = blockIdx.y * 128;

    float acc[2][8][4];
#pragma unroll
    for (int mt = 0; mt < 2; mt++)
#pragma unroll
        for (int nt = 0; nt < 8; nt++)
#pragma unroll
            for (int c = 0; c < 4; c++) acc[mt][nt][c] = 0.f;

    const int lr = lane & 15;                 // ldmatrix row within 16
    const int lc = (lane >> 4) * 16;          // ldmatrix 16B col select

    // per-thread load coords (fixed across chunks)
    const int br = tid >> 1, bc = tid & 1;    // B: 128 rows x 2 x 16B... (see below)

    // ---- B tile cp.async issue for chunk ch into stage s ----
    auto load_B = [&](int ch, int s) {
        char* dst = smem + s * 65536;
#pragma unroll
        for (int it = 0; it < 4; it++) {
            int t = tid + it * 256;           // 0..1023
            int r = t >> 3, c = t & 7;
            uint32_t doff = swz128((uint32_t)(r * 128 + c * 16));
            cpa16(sb + s * 65536 + 32768 + doff,
                  (const uint4*)Bhi + (size_t)(n0 + r) * 128 + ch * 8 + c);
            cpa16(sb + s * 65536 + 49152 + doff,
                  (const uint4*)Blo + (size_t)(n0 + r) * 128 + ch * 8 + c);
        }
        (void)dst;
    };
    // ---- A fp32 prefetch to regs ----
    auto load_A = [&](int ch, float4* areg) {
#pragma unroll
        for (int it = 0; it < 8; it++) {
            int idx = tid + it * 256;         // 0..2047
            int r = idx >> 4, c4 = idx & 15;
            areg[it] = ((const float4*)(X + (size_t)(m0 + r) * DM + ch * 64))[c4];
        }
    };
    // ---- A split + STS into stage s ----
    auto store_A = [&](const float4* areg, int s) {
#pragma unroll
        for (int it = 0; it < 8; it++) {
            int idx = tid + it * 256;
            int r = idx >> 4, c4 = idx & 15;
            uint2 h, l;
            split2(areg[it].x, areg[it].y, h.x, l.x);
            split2(areg[it].z, areg[it].w, h.y, l.y);
            uint32_t off = swz128((uint32_t)(r * 128 + c4 * 8));
            *(uint2*)(smem + s * 65536 + off) = h;
            *(uint2*)(smem + s * 65536 + 16384 + off) = l;
        }
    };

    // prologue: stage 0 fully loaded
    {
        float4 areg[8];
        load_B(0, 0);
        cpa_commit();
        load_A(0, areg);
        store_A(areg, 0);
        cpa_wait0();
    }
    __syncthreads();

    for (int ch = 0; ch < GK_NCH; ch++) {
        const int s = ch & 1;
        const uint32_t base = sb + s * 65536;
        const bool has_next = (ch + 1 < GK_NCH);

        float4 areg[8];
        if (has_next) {
            load_B(ch + 1, s ^ 1);            // async, overlaps MMAs
            cpa_commit();
            load_A(ch + 1, areg);             // LDG latency hidden under MMAs
        }

        // ---- MMA phase on stage s ----
#pragma unroll
        for (int kk = 0; kk < 4; kk++) {
            uint32_t ah[2][4], al[2][4], bh[8][2], bl[8][2];
#pragma unroll
            for (int mt = 0; mt < 2; mt++) {
                uint32_t off = (uint32_t)(wm + mt * 16 + lr) * 128 + kk * 32 + lc;
                uint32_t so = swz128(off);
                ldsm4(ah[mt], base + so);
                ldsm4(al[mt], base + 16384 + so);
            }
#pragma unroll
            for (int g = 0; g < 4; g++) {
                uint32_t off = (uint32_t)(wn + g * 16 + lr) * 128 + kk * 32 + lc;
                uint32_t so = swz128(off);
                uint32_t t4[4];
                ldsm4(t4, base + 32768 + so);
                bh[2*g][0] = t4[0]; bh[2*g][1] = t4[2];
                bh[2*g+1][0] = t4[1]; bh[2*g+1][1] = t4[3];
                ldsm4(t4, base + 49152 + so);
                bl[2*g][0] = t4[0]; bl[2*g][1] = t4[2];
                bl[2*g+1][0] = t4[1]; bl[2*g+1][1] = t4[3];
            }
#pragma unroll
            for (int mt = 0; mt < 2; mt++)
#pragma unroll
                for (int nt = 0; nt < 8; nt++) {
                    mma_bf16(acc[mt][nt], ah[mt], bh[nt][0], bh[nt][1]);
                    mma_bf16(acc[mt][nt], ah[mt], bl[nt][0], bl[nt][1]);
                    mma_bf16(acc[mt][nt], al[mt], bh[nt][0], bh[nt][1]);
                }
        }

        if (has_next) {
            store_A(areg, s ^ 1);
            cpa_wait0();
        }
        __syncthreads();
    }

#pragma unroll
    for (int mt = 0; mt < 2; mt++) {
#pragma unroll
        for (int half = 0; half < 2; half++) {
            int m = m0 + wm + mt * 16 + (lane >> 2) + half * 8;
            int b_ = m / Ss, s_ = m - b_ * Ss;
#pragma unroll
            for (int nt = 0; nt < 8; nt++) {
                int n = n0 + wn + nt * 8 + (lane & 3) * 2;
                float v0 = acc[mt][nt][half * 2 + 0] + bias[n];
                float v1 = acc[mt][nt][half * 2 + 1] + bias[n + 1];
                if (MODE == 0) {
                    C[(size_t)m * DM + n]     = v0;
                    C[(size_t)m * DM + n + 1] = v1;
                } else {
                    int h = n >> 6, d = n & 63;
                    size_t base2 = (((size_t)b_ * Hh + h) * Ss + s_) * HD + d;
                    uint32_t hi, lo;
                    split2(v0, v1, hi, lo);   // d even -> 4B-aligned pair
                    *(uint32_t*)(Chi + base2) = hi;
                    *(uint32_t*)(Clo + base2) = lo;
                }
            }
        }
    }
}

// ---------------------------------------------------------------------------
// Flash attention (causal), split-bf16 mma.sync, pre-split inputs,
// DOUBLE-BUFFERED KV via cp.async groups.
// Smem: Qhi@0 Qlo@16K; KV stage s at 32768+s*32768 (Khi,Klo,Vhi,Vlo x 8KB).
// Total 96KB.
// ---------------------------------------------------------------------------
#define FM_SMEM_BYTES 98304

__global__ __launch_bounds__(256) void flash_mma(
    const __nv_bfloat16* __restrict__ Qhi, const __nv_bfloat16* __restrict__ Qlo,
    const __nv_bfloat16* __restrict__ Khi, const __nv_bfloat16* __restrict__ Klo,
    const __nv_bfloat16* __restrict__ Vhi, const __nv_bfloat16* __restrict__ Vlo,
    float* __restrict__ OUT)
{
    char* smem = dyn_smem;
    const uint32_t sb = smem_to_u32(smem);
    const int tid = threadIdx.x, lane = tid & 31, w = tid >> 5;
    const int qi = (int)gridDim.x - 1 - (int)blockIdx.x;   // heavy tiles first
    const int bh = blockIdx.y;
    const int b_ = bh / Hh, h_ = bh & (Hh - 1);
    const int s0 = qi * 128;
    const int lr = lane & 15, lc = (lane >> 4) * 16;

    const uint32_t sQhi = sb, sQlo = sb + 16384;

    // KV prefetch into stage s
    auto load_KV = [&](int kt, int s) {
        const size_t roff = ((size_t)bh * Ss + kt * 64) * HD;
        const uint4* srcs[4] = {
            (const uint4*)(Khi + roff), (const uint4*)(Klo + roff),
            (const uint4*)(Vhi + roff), (const uint4*)(Vlo + roff) };
        const uint32_t kbase = sb + 32768 + s * 32768;
#pragma unroll
        for (int it = 0; it < 8; it++) {
            int idx = tid + it * 256;     // 0..2047
            int buf = idx >> 9;           // 0..3
            int j = idx & 511;
            int r = j >> 3, c = j & 7;
            uint32_t doff = swz128((uint32_t)(r * 128 + c * 16));
            cpa16(kbase + buf * 8192 + doff, srcs[buf] + r * 8 + c);
        }
    };

    // Q tiles (own cp.async group, oldest)
    {
        const uint4* q0 = (const uint4*)(Qhi + ((size_t)bh * Ss + s0) * HD);
        const uint4* q1 = (const uint4*)(Qlo + ((size_t)bh * Ss + s0) * HD);
#pragma unroll
        for (int it = 0; it < 4; it++) {
            int t = tid + it * 256;           // 0..1023
            int r = t >> 3, c = t & 7;
            uint32_t doff = swz128((uint32_t)(r * 128 + c * 16));
            cpa16(sQhi + doff, q0 + r * 8 + c);
            cpa16(sQlo + doff, q1 + r * 8 + c);
        }
        cpa_commit();
    }

    const int nkt = 2 * qi + 2;
    load_KV(0, 0);
    cpa_commit();

    float m0 = -1e30f, m1 = -1e30f, l0 = 0.f, l1 = 0.f;
    float o[8][4];
#pragma unroll
    for (int nt = 0; nt < 8; nt++)
#pragma unroll
        for (int c = 0; c < 4; c++) o[nt][c] = 0.f;

    const int row0 = s0 + w * 16 + (lane >> 2);

    for (int kt = 0; kt < nkt; kt++) {
        const int s = kt & 1;
        const uint32_t sKhi = sb + 32768 + s * 32768;
        const uint32_t sKlo = sKhi + 8192;
        const uint32_t sVhi = sKhi + 16384;
        const uint32_t sVlo = sKhi + 24576;

        __syncthreads();                      // all warps done reading stage s^1
        if (kt + 1 < nkt) {
            load_KV(kt + 1, s ^ 1);           // overlaps compute of kt
            cpa_commit();
            cpa_wait1();                      // kt's stage (and Q) complete
        } else {
            cpa_wait0();
        }
        __syncthreads();

        // ---- S = Q K^T (warp: 16 rows x 64 cols), split 3-term ----
        float sa[8][4];
#pragma unroll
        for (int nt = 0; nt < 8; nt++)
#pragma unroll
            for (int c = 0; c < 4; c++) sa[nt][c] = 0.f;

#pragma unroll
        for (int kk = 0; kk < 4; kk++) {
            uint32_t ah[4], al[4];
            uint32_t aoff = swz128((uint32_t)((w * 16 + lr) * 128 + kk * 32 + lc));
            ldsm4(ah, sQhi + aoff);
            ldsm4(al, sQlo + aoff);
#pragma unroll
            for (int g = 0; g < 4; g++) {
                uint32_t koff = swz128((uint32_t)((g * 16 + lr) * 128 + kk * 32 + lc));
                uint32_t th[4], tl[4];
                ldsm4(th, sKhi + koff);
                ldsm4(tl, sKlo + koff);
                mma_bf16(sa[2*g],   ah, th[0], th[2]);
                mma_bf16(sa[2*g],   ah, tl[0], tl[2]);
                mma_bf16(sa[2*g],   al, th[0], th[2]);
                mma_bf16(sa[2*g+1], ah, th[1], th[3]);
                mma_bf16(sa[2*g+1], ah, tl[1], tl[3]);
                mma_bf16(sa[2*g+1], al, th[1], th[3]);
            }
        }
        // scale by 1/sqrt(1024)
#pragma unroll
        for (int nt = 0; nt < 8; nt++)
#pragma unroll
            for (int c = 0; c < 4; c++) sa[nt][c] *= 0.03125f;

        // ---- causal mask (only last two k-tiles can cross the diagonal) ----
        if (kt >= 2 * qi) {
#pragma unroll
            for (int nt = 0; nt < 8; nt++) {
                int colb = kt * 64 + nt * 8 + (lane & 3) * 2;
                if (colb     > row0)     sa[nt][0] = -1e9f;
                if (colb + 1 > row0)     sa[nt][1] = -1e9f;
                if (colb     > row0 + 8) sa[nt][2] = -1e9f;
                if (colb + 1 > row0 + 8) sa[nt][3] = -1e9f;
            }
        }

        // ---- online softmax (rows row0, row0+8; 4-lane reductions) ----
        float mx0 = -1e30f, mx1 = -1e30f;
#pragma unroll
        for (int nt = 0; nt < 8; nt++) {
            mx0 = fmaxf(mx0, fmaxf(sa[nt][0], sa[nt][1]));
            mx1 = fmaxf(mx1, fmaxf(sa[nt][2], sa[nt][3]));
        }
        mx0 = fmaxf(mx0, __shfl_xor_sync(0xffffffffu, mx0, 1));
        mx0 = fmaxf(mx0, __shfl_xor_sync(0xffffffffu, mx0, 2));
        mx1 = fmaxf(mx1, __shfl_xor_sync(0xffffffffu, mx1, 1));
        mx1 = fmaxf(mx1, __shfl_xor_sync(0xffffffffu, mx1, 2));
        float mn0 = fmaxf(m0, mx0), mn1 = fmaxf(m1, mx1);
        float c0 = __expf(m0 - mn0), c1 = __expf(m1 - mn1);
        float rs0 = 0.f, rs1 = 0.f;
#pragma unroll
        for (int nt = 0; nt < 8; nt++) {
            sa[nt][0] = __expf(sa[nt][0] - mn0); rs0 += sa[nt][0];
            sa[nt][1] = __expf(sa[nt][1] - mn0); rs0 += sa[nt][1];
            sa[nt][2] = __expf(sa[nt][2] - mn1); rs1 += sa[nt][2];
            sa[nt][3] = __expf(sa[nt][3] - mn1); rs1 += sa[nt][3];
        }
        rs0 += __shfl_xor_sync(0xffffffffu, rs0, 1);
        rs0 += __shfl_xor_sync(0xffffffffu, rs0, 2);
        rs1 += __shfl_xor_sync(0xffffffffu, rs1, 1);
        rs1 += __shfl_xor_sync(0xffffffffu, rs1, 2);
        l0 = l0 * c0 + rs0; l1 = l1 * c1 + rs1;
        m0 = mn0; m1 = mn1;
#pragma unroll
        for (int nt = 0; nt < 8; nt++) {
            o[nt][0] *= c0; o[nt][1] *= c0;
            o[nt][2] *= c1; o[nt][3] *= c1;
        }

        // ---- O += P V  (P frags from registers; V via ldmatrix.trans) ----
#pragma unroll
        for (int k2 = 0; k2 < 4; k2++) {
            uint32_t phi[4], plo[4];
            split2(sa[2*k2][0],   sa[2*k2][1],   phi[0], plo[0]);
            split2(sa[2*k2][2],   sa[2*k2][3],   phi[1], plo[1]);
            split2(sa[2*k2+1][0], sa[2*k2+1][1], phi[2], plo[2]);
            split2(sa[2*k2+1][2], sa[2*k2+1][3], phi[3], plo[3]);
#pragma unroll
            for (int u = 0; u < 4; u++) {
                uint32_t voff = swz128((uint32_t)((k2 * 16 + lr) * 128 + u * 32 + lc));
                uint32_t th[4], tl[4];
                ldsm4t(th, sVhi + voff);
                ldsm4t(tl, sVlo + voff);
                mma_bf16(o[2*u],   phi, th[0], th[1]);
                mma_bf16(o[2*u],   phi, tl[0], tl[1]);
                mma_bf16(o[2*u],   plo, th[0], th[1]);
                mma_bf16(o[2*u+1], phi, th[2], th[3]);
                mma_bf16(o[2*u+1], phi, tl[2], tl[3]);
                mma_bf16(o[2*u+1], plo, th[2], th[3]);
            }
        }
    }

    // ---- epilogue: normalize, write [B,S, h*64+d] ----
    float i0 = 1.f / l0, i1 = 1.f / l1;
    float* O0 = OUT + ((size_t)b_ * Ss + row0) * DM + h_ * HD;
    float* O1 = O0 + 8 * DM;
#pragma unroll
    for (int nt = 0; nt < 8; nt++) {
        int d = nt * 8 + (lane & 3) * 2;
        float2 a; a.x = o[nt][0] * i0; a.y = o[nt][1] * i0;
        float2 b; b.x = o[nt][2] * i1; b.y = o[nt][3] * i1;
        *(float2*)(O0 + d) = a;
        *(float2*)(O1 + d) = b;
    }
}

// ---------------------------------------------------------------------------
extern "C" void kernel_launch(void* const* d_in, const int* in_sizes, int n_in,
                              void* d_out, int out_size)
{
    const float* queries = (const float*)d_in[0];
    const float* keys    = (const float*)d_in[1];
    const float* values  = (const float*)d_in[2];
    // d_in[3] = mask (causal triu) — computed arithmetically instead
    const float* Wq = (const float*)d_in[4];
    const float* bq = (const float*)d_in[5];
    const float* Wk = (const float*)d_in[6];
    const float* bk = (const float*)d_in[7];
    const float* Wv = (const float*)d_in[8];
    const float* bv = (const float*)d_in[9];
    const float* Wo = (const float*)d_in[10];
    const float* bo = (const float*)d_in[11];

    // One-time host setup: cache scratch pointers + smem attributes.
    // (Caches pointers only — every call enqueues identical work.)
    static float* att = nullptr;
    static __nv_bfloat16 *qhi, *qlo, *khi, *klo, *vhi, *vlo, *bhi, *blo;
    if (att == nullptr) {
        cudaGetSymbolAddress((void**)&qhi, g_Qhi);
        cudaGetSymbolAddress((void**)&qlo, g_Qlo);
        cudaGetSymbolAddress((void**)&khi, g_Khi);
        cudaGetSymbolAddress((void**)&klo, g_Klo);
        cudaGetSymbolAddress((void**)&vhi, g_Vhi);
        cudaGetSymbolAddress((void**)&vlo, g_Vlo);
        cudaGetSymbolAddress((void**)&att, g_att);
        cudaGetSymbolAddress((void**)&bhi, g_Bhi);
        cudaGetSymbolAddress((void**)&blo, g_Blo);
        cudaFuncSetAttribute(flash_mma,
                             cudaFuncAttributeMaxDynamicSharedMemorySize,
                             FM_SMEM_BYTES);
        cudaFuncSetAttribute(gemm_mma<0>,
                             cudaFuncAttributeMaxDynamicSharedMemorySize,
                             G_SMEM_TOTAL);
        cudaFuncSetAttribute(gemm_mma<1>,
                             cudaFuncAttributeMaxDynamicSharedMemorySize,
                             G_SMEM_TOTAL);
    }

    dim3 wgrid(DM / 32, DM / 32), wblk(32, 8);
    dim3 ggrid(DM / 128, NROWS / 128);             // (8, 32)

    // Q projection -> split bf16 [B,H,S,64]
    conv_w_t<<<wgrid, wblk>>>(Wq, bhi, blo);
    gemm_mma<1><<<ggrid, 256, G_SMEM_TOTAL>>>(queries, bhi, blo, bq,
                                              nullptr, qhi, qlo);
    // K projection
    conv_w_t<<<wgrid, wblk>>>(Wk, bhi, blo);
    gemm_mma<1><<<ggrid, 256, G_SMEM_TOTAL>>>(keys, bhi, blo, bk,
                                              nullptr, khi, klo);
    // V projection
    conv_w_t<<<wgrid, wblk>>>(Wv, bhi, blo);
    gemm_mma<1><<<ggrid, 256, G_SMEM_TOTAL>>>(values, bhi, blo, bv,
                                              nullptr, vhi, vlo);

    // Attention (split-bf16 tensor-core flash, pre-split, double-buffered)
    flash_mma<<<dim3(Ss / 128, Bb * Hh), 256, FM_SMEM_BYTES>>>(
        qhi, qlo, khi, klo, vhi, vlo, att);

    // Output projection (fp32 att in, fp32 out)
    conv_w_t<<<wgrid, wblk>>>(Wo, bhi, blo);
    gemm_mma<0><<<ggrid, 256, G_SMEM_TOTAL>>>(att, bhi, blo, bo,
                                              (float*)d_out, nullptr, nullptr);
}

// round 17
// speedup vs baseline: 3.0398x; 1.0084x over previous
#include <cuda_runtime.h>
#include <cuda_bf16.h>
#include <cstdint>

#define Bb 2
#define Ss 2048
#define DM 1024
#define Hh 16
#define HD 64
#define NROWS (Bb*Ss)

// ---------------------------------------------------------------------------
// Scratch (device globals — no allocations allowed)
// ---------------------------------------------------------------------------
__device__ __nv_bfloat16 g_Qhi[Bb*Hh*Ss*HD], g_Qlo[Bb*Hh*Ss*HD];
__device__ __nv_bfloat16 g_Khi[Bb*Hh*Ss*HD], g_Klo[Bb*Hh*Ss*HD];
__device__ __nv_bfloat16 g_Vhi[Bb*Hh*Ss*HD], g_Vlo[Bb*Hh*Ss*HD];
__device__ float g_att[NROWS*DM];           // attention output, [B,S, H*64]
// split+transposed weights [n][k], one pair per projection
__device__ __nv_bfloat16 g_BhiQ[DM*DM], g_BloQ[DM*DM];
__device__ __nv_bfloat16 g_BhiK[DM*DM], g_BloK[DM*DM];
__device__ __nv_bfloat16 g_BhiV[DM*DM], g_BloV[DM*DM];
__device__ __nv_bfloat16 g_BhiO[DM*DM], g_BloO[DM*DM];

// Single dynamic-smem symbol shared by all kernels (type must agree TU-wide)
extern __shared__ char dyn_smem[];

// ---------------------------------------------------------------------------
// Helpers
// ---------------------------------------------------------------------------
__device__ __forceinline__ uint32_t smem_to_u32(const void* p) {
    uint32_t a;
    asm("{ .reg .u64 t; cvta.to.shared.u64 t, %1; cvt.u32.u64 %0, t; }"
        : "=r"(a) : "l"(p));
    return a;
}
__device__ __forceinline__ uint32_t swz128(uint32_t o) {
    return o ^ ((o >> 3) & 0x70);
}
__device__ __forceinline__ void ldsm4(uint32_t* r, uint32_t addr) {
    asm volatile("ldmatrix.sync.aligned.m8n8.x4.shared.b16 {%0,%1,%2,%3}, [%4];"
                 : "=r"(r[0]), "=r"(r[1]), "=r"(r[2]), "=r"(r[3]) : "r"(addr));
}
__device__ __forceinline__ void ldsm4t(uint32_t* r, uint32_t addr) {
    asm volatile("ldmatrix.sync.aligned.m8n8.x4.trans.shared.b16 {%0,%1,%2,%3}, [%4];"
                 : "=r"(r[0]), "=r"(r[1]), "=r"(r[2]), "=r"(r[3]) : "r"(addr));
}
// D (+)= A(m16k16,row) * B(k16n8,col) ; bf16 in, fp32 accum
__device__ __forceinline__ void mma_bf16(float* d, const uint32_t* a,
                                         const uint32_t b0, const uint32_t b1) {
    asm volatile(
        "mma.sync.aligned.m16n8k16.row.col.f32.bf16.bf16.f32 "
        "{%0,%1,%2,%3}, {%4,%5,%6,%7}, {%8,%9}, {%0,%1,%2,%3};"
        : "+f"(d[0]), "+f"(d[1]), "+f"(d[2]), "+f"(d[3])
        : "r"(a[0]), "r"(a[1]), "r"(a[2]), "r"(a[3]), "r"(b0), "r"(b1));
}
// split two fp32 into packed bf16x2 hi + residual lo (f0 in low half)
__device__ __forceinline__ void split2(float f0, float f1, uint32_t& hi, uint32_t& lo) {
    __nv_bfloat162 h = __floats2bfloat162_rn(f0, f1);
    float r0 = f0 - __bfloat162float(__low2bfloat16(h));
    float r1 = f1 - __bfloat162float(__high2bfloat16(h));
    __nv_bfloat162 l = __floats2bfloat162_rn(r0, r1);
    hi = *(uint32_t*)&h; lo = *(uint32_t*)&l;
}
// cp.async 16B gmem -> smem
__device__ __forceinline__ void cpa16(uint32_t dst, const void* src) {
    asm volatile("cp.async.cg.shared.global [%0], [%1], 16;"
                 :: "r"(dst), "l"(src) : "memory");
}
__device__ __forceinline__ void cpa_commit() {
    asm volatile("cp.async.commit_group;" ::: "memory");
}
__device__ __forceinline__ void cpa_wait0() {
    asm volatile("cp.async.wait_group 0;" ::: "memory");
}
__device__ __forceinline__ void cpa_wait1() {
    asm volatile("cp.async.wait_group 1;" ::: "memory");
}

// ---------------------------------------------------------------------------
// W[k][n] fp32 -> out[n][k] bf16 hi/lo (transpose + split)
// ---------------------------------------------------------------------------
__global__ __launch_bounds__(256) void conv_w_t(
    const float* __restrict__ W, __nv_bfloat16* __restrict__ Hi,
    __nv_bfloat16* __restrict__ Lo)
{
    __shared__ float t[32][33];
    const int tx = threadIdx.x, ty = threadIdx.y;           // 32 x 8
    const int n0 = blockIdx.x * 32, k0 = blockIdx.y * 32;
#pragma unroll
    for (int r = ty; r < 32; r += 8)
        t[r][tx] = W[(size_t)(k0 + r) * DM + n0 + tx];
    __syncthreads();
#pragma unroll
    for (int r = ty; r < 32; r += 8) {
        float v = t[tx][r];                                  // W[k0+tx][n0+r]
        __nv_bfloat16 h = __float2bfloat16(v);
        __nv_bfloat16 l = __float2bfloat16(v - __bfloat162float(h));
        size_t o = (size_t)(n0 + r) * DM + k0 + tx;
        Hi[o] = h; Lo[o] = l;
    }
}

// ---------------------------------------------------------------------------
// GEMM core (double-buffered, 3-MMA split-bf16), shared by both kernels.
//   X fp32 row-major; B split bf16 [n][k]; CTA 128x128, K-chunk 64.
// MODE 0: write fp32 C row-major.  MODE 1: split bf16 Chi/Clo [B,H,S,64].
// ---------------------------------------------------------------------------
#define G_SMEM_TOTAL 131072   // stage s at s*65536: Ahi@0 Alo@16K Bhi@32K Blo@48K
#define GK_NCH (DM / 64)      // 16

template <int MODE>
__device__ __forceinline__ void gemm_core(
    char* smem,
    const float* __restrict__ X,
    const __nv_bfloat16* __restrict__ Bhi, const __nv_bfloat16* __restrict__ Blo,
    const float* __restrict__ bias, float* __restrict__ C,
    __nv_bfloat16* __restrict__ Chi, __nv_bfloat16* __restrict__ Clo,
    int m0, int n0)
{
    const uint32_t sb = smem_to_u32(smem);
    const int tid = threadIdx.x;
    const int lane = tid & 31, wid = tid >> 5;
    const int wm = (wid >> 1) * 32;          // warp m offset: 0,32,64,96
    const int wn = (wid & 1) * 64;           // warp n offset: 0,64

    float acc[2][8][4];
#pragma unroll
    for (int mt = 0; mt < 2; mt++)
#pragma unroll
        for (int nt = 0; nt < 8; nt++)
#pragma unroll
            for (int c = 0; c < 4; c++) acc[mt][nt][c] = 0.f;

    const int lr = lane & 15;                 // ldmatrix row within 16
    const int lc = (lane >> 4) * 16;          // ldmatrix 16B col select

    auto load_B = [&](int ch, int s) {
#pragma unroll
        for (int it = 0; it < 4; it++) {
            int t = tid + it * 256;           // 0..1023
            int r = t >> 3, c = t & 7;
            uint32_t doff = swz128((uint32_t)(r * 128 + c * 16));
            cpa16(sb + s * 65536 + 32768 + doff,
                  (const uint4*)Bhi + (size_t)(n0 + r) * 128 + ch * 8 + c);
            cpa16(sb + s * 65536 + 49152 + doff,
                  (const uint4*)Blo + (size_t)(n0 + r) * 128 + ch * 8 + c);
        }
    };
    auto load_A = [&](int ch, float4* areg) {
#pragma unroll
        for (int it = 0; it < 8; it++) {
            int idx = tid + it * 256;         // 0..2047
            int r = idx >> 4, c4 = idx & 15;
            areg[it] = ((const float4*)(X + (size_t)(m0 + r) * DM + ch * 64))[c4];
        }
    };
    auto store_A = [&](const float4* areg, int s) {
#pragma unroll
        for (int it = 0; it < 8; it++) {
            int idx = tid + it * 256;
            int r = idx >> 4, c4 = idx & 15;
            uint2 h, l;
            split2(areg[it].x, areg[it].y, h.x, l.x);
            split2(areg[it].z, areg[it].w, h.y, l.y);
            uint32_t off = swz128((uint32_t)(r * 128 + c4 * 8));
            *(uint2*)(smem + s * 65536 + off) = h;
            *(uint2*)(smem + s * 65536 + 16384 + off) = l;
        }
    };

    {
        float4 areg[8];
        load_B(0, 0);
        cpa_commit();
        load_A(0, areg);
        store_A(areg, 0);
        cpa_wait0();
    }
    __syncthreads();

    for (int ch = 0; ch < GK_NCH; ch++) {
        const int s = ch & 1;
        const uint32_t base = sb + s * 65536;
        const bool has_next = (ch + 1 < GK_NCH);

        float4 areg[8];
        if (has_next) {
            load_B(ch + 1, s ^ 1);
            cpa_commit();
            load_A(ch + 1, areg);
        }

#pragma unroll
        for (int kk = 0; kk < 4; kk++) {
            uint32_t ah[2][4], al[2][4], bh[8][2], bl[8][2];
#pragma unroll
            for (int mt = 0; mt < 2; mt++) {
                uint32_t off = (uint32_t)(wm + mt * 16 + lr) * 128 + kk * 32 + lc;
                uint32_t so = swz128(off);
                ldsm4(ah[mt], base + so);
                ldsm4(al[mt], base + 16384 + so);
            }
#pragma unroll
            for (int g = 0; g < 4; g++) {
                uint32_t off = (uint32_t)(wn + g * 16 + lr) * 128 + kk * 32 + lc;
                uint32_t so = swz128(off);
                uint32_t t4[4];
                ldsm4(t4, base + 32768 + so);
                bh[2*g][0] = t4[0]; bh[2*g][1] = t4[2];
                bh[2*g+1][0] = t4[1]; bh[2*g+1][1] = t4[3];
                ldsm4(t4, base + 49152 + so);
                bl[2*g][0] = t4[0]; bl[2*g][1] = t4[2];
                bl[2*g+1][0] = t4[1]; bl[2*g+1][1] = t4[3];
            }
#pragma unroll
            for (int mt = 0; mt < 2; mt++)
#pragma unroll
                for (int nt = 0; nt < 8; nt++) {
                    mma_bf16(acc[mt][nt], ah[mt], bh[nt][0], bh[nt][1]);
                    mma_bf16(acc[mt][nt], ah[mt], bl[nt][0], bl[nt][1]);
                    mma_bf16(acc[mt][nt], al[mt], bh[nt][0], bh[nt][1]);
                }
        }

        if (has_next) {
            store_A(areg, s ^ 1);
            cpa_wait0();
        }
        __syncthreads();
    }

#pragma unroll
    for (int mt = 0; mt < 2; mt++) {
#pragma unroll
        for (int half = 0; half < 2; half++) {
            int m = m0 + wm + mt * 16 + (lane >> 2) + half * 8;
            int b_ = m / Ss, s_ = m - b_ * Ss;
#pragma unroll
            for (int nt = 0; nt < 8; nt++) {
                int n = n0 + wn + nt * 8 + (lane & 3) * 2;
                float v0 = acc[mt][nt][half * 2 + 0] + bias[n];
                float v1 = acc[mt][nt][half * 2 + 1] + bias[n + 1];
                if (MODE == 0) {
                    C[(size_t)m * DM + n]     = v0;
                    C[(size_t)m * DM + n + 1] = v1;
                } else {
                    int h = n >> 6, d = n & 63;
                    size_t base2 = (((size_t)b_ * Hh + h) * Ss + s_) * HD + d;
                    uint32_t hi, lo;
                    split2(v0, v1, hi, lo);   // d even -> 4B-aligned pair
                    *(uint32_t*)(Chi + base2) = hi;
                    *(uint32_t*)(Clo + base2) = lo;
                }
            }
        }
    }
}

// Fused Q/K/V projection: blockIdx.z selects the projection. 768 CTAs pack
// as one 5.19-wave launch instead of three 1.73-wave launches.
__global__ __launch_bounds__(256, 1) void gemm_qkv(
    const float* __restrict__ Xq, const float* __restrict__ Xk,
    const float* __restrict__ Xv,
    const float* __restrict__ bq, const float* __restrict__ bk,
    const float* __restrict__ bv)
{
    const int z = blockIdx.z;
    const float* X    = (z == 0) ? Xq : (z == 1) ? Xk : Xv;
    const float* bias = (z == 0) ? bq : (z == 1) ? bk : bv;
    const __nv_bfloat16* Bhi = (z == 0) ? g_BhiQ : (z == 1) ? g_BhiK : g_BhiV;
    const __nv_bfloat16* Blo = (z == 0) ? g_BloQ : (z == 1) ? g_BloK : g_BloV;
    __nv_bfloat16* Chi = (z == 0) ? g_Qhi : (z == 1) ? g_Khi : g_Vhi;
    __nv_bfloat16* Clo = (z == 0) ? g_Qlo : (z == 1) ? g_Klo : g_Vlo;
    gemm_core<1>(dyn_smem, X, Bhi, Blo, bias, nullptr, Chi, Clo,
                 blockIdx.y * 128, blockIdx.x * 128);
}

// Output projection (fp32 in/out)
__global__ __launch_bounds__(256, 1) void gemm_out(
    const float* __restrict__ X, const float* __restrict__ bias,
    float* __restrict__ C)
{
    gemm_core<0>(dyn_smem, X, g_BhiO, g_BloO, bias, C, nullptr, nullptr,
                 blockIdx.y * 128, blockIdx.x * 128);
}

// ---------------------------------------------------------------------------
// Flash attention (causal), split-bf16 mma.sync, pre-split inputs,
// double-buffered KV via cp.async groups. Smem 96KB. (Unchanged.)
// ---------------------------------------------------------------------------
#define FM_SMEM_BYTES 98304

__global__ __launch_bounds__(256) void flash_mma(
    const __nv_bfloat16* __restrict__ Qhi, const __nv_bfloat16* __restrict__ Qlo,
    const __nv_bfloat16* __restrict__ Khi, const __nv_bfloat16* __restrict__ Klo,
    const __nv_bfloat16* __restrict__ Vhi, const __nv_bfloat16* __restrict__ Vlo,
    float* __restrict__ OUT)
{
    char* smem = dyn_smem;
    const uint32_t sb = smem_to_u32(smem);
    const int tid = threadIdx.x, lane = tid & 31, w = tid >> 5;
    const int qi = (int)gridDim.x - 1 - (int)blockIdx.x;   // heavy tiles first
    const int bh = blockIdx.y;
    const int b_ = bh / Hh, h_ = bh & (Hh - 1);
    const int s0 = qi * 128;
    const int lr = lane & 15, lc = (lane >> 4) * 16;

    const uint32_t sQhi = sb, sQlo = sb + 16384;

    auto load_KV = [&](int kt, int s) {
        const size_t roff = ((size_t)bh * Ss + kt * 64) * HD;
        const uint4* srcs[4] = {
            (const uint4*)(Khi + roff), (const uint4*)(Klo + roff),
            (const uint4*)(Vhi + roff), (const uint4*)(Vlo + roff) };
        const uint32_t kbase = sb + 32768 + s * 32768;
#pragma unroll
        for (int it = 0; it < 8; it++) {
            int idx = tid + it * 256;     // 0..2047
            int buf = idx >> 9;           // 0..3
            int j = idx & 511;
            int r = j >> 3, c = j & 7;
            uint32_t doff = swz128((uint32_t)(r * 128 + c * 16));
            cpa16(kbase + buf * 8192 + doff, srcs[buf] + r * 8 + c);
        }
    };

    // Q tiles (own cp.async group, oldest)
    {
        const uint4* q0 = (const uint4*)(Qhi + ((size_t)bh * Ss + s0) * HD);
        const uint4* q1 = (const uint4*)(Qlo + ((size_t)bh * Ss + s0) * HD);
#pragma unroll
        for (int it = 0; it < 4; it++) {
            int t = tid + it * 256;           // 0..1023
            int r = t >> 3, c = t & 7;
            uint32_t doff = swz128((uint32_t)(r * 128 + c * 16));
            cpa16(sQhi + doff, q0 + r * 8 + c);
            cpa16(sQlo + doff, q1 + r * 8 + c);
        }
        cpa_commit();
    }

    const int nkt = 2 * qi + 2;
    load_KV(0, 0);
    cpa_commit();

    float m0 = -1e30f, m1 = -1e30f, l0 = 0.f, l1 = 0.f;
    float o[8][4];
#pragma unroll
    for (int nt = 0; nt < 8; nt++)
#pragma unroll
        for (int c = 0; c < 4; c++) o[nt][c] = 0.f;

    const int row0 = s0 + w * 16 + (lane >> 2);

    for (int kt = 0; kt < nkt; kt++) {
        const int s = kt & 1;
        const uint32_t sKhi = sb + 32768 + s * 32768;
        const uint32_t sKlo = sKhi + 8192;
        const uint32_t sVhi = sKhi + 16384;
        const uint32_t sVlo = sKhi + 24576;

        __syncthreads();
        if (kt + 1 < nkt) {
            load_KV(kt + 1, s ^ 1);
            cpa_commit();
            cpa_wait1();
        } else {
            cpa_wait0();
        }
        __syncthreads();

        // ---- S = Q K^T ----
        float sa[8][4];
#pragma unroll
        for (int nt = 0; nt < 8; nt++)
#pragma unroll
            for (int c = 0; c < 4; c++) sa[nt][c] = 0.f;

#pragma unroll
        for (int kk = 0; kk < 4; kk++) {
            uint32_t ah[4], al[4];
            uint32_t aoff = swz128((uint32_t)((w * 16 + lr) * 128 + kk * 32 + lc));
            ldsm4(ah, sQhi + aoff);
            ldsm4(al, sQlo + aoff);
#pragma unroll
            for (int g = 0; g < 4; g++) {
                uint32_t koff = swz128((uint32_t)((g * 16 + lr) * 128 + kk * 32 + lc));
                uint32_t th[4], tl[4];
                ldsm4(th, sKhi + koff);
                ldsm4(tl, sKlo + koff);
                mma_bf16(sa[2*g],   ah, th[0], th[2]);
                mma_bf16(sa[2*g],   ah, tl[0], tl[2]);
                mma_bf16(sa[2*g],   al, th[0], th[2]);
                mma_bf16(sa[2*g+1], ah, th[1], th[3]);
                mma_bf16(sa[2*g+1], ah, tl[1], tl[3]);
                mma_bf16(sa[2*g+1], al, th[1], th[3]);
            }
        }
#pragma unroll
        for (int nt = 0; nt < 8; nt++)
#pragma unroll
            for (int c = 0; c < 4; c++) sa[nt][c] *= 0.03125f;

        // ---- causal mask ----
        if (kt >= 2 * qi) {
#pragma unroll
            for (int nt = 0; nt < 8; nt++) {
                int colb = kt * 64 + nt * 8 + (lane & 3) * 2;
                if (colb     > row0)     sa[nt][0] = -1e9f;
                if (colb + 1 > row0)     sa[nt][1] = -1e9f;
                if (colb     > row0 + 8) sa[nt][2] = -1e9f;
                if (colb + 1 > row0 + 8) sa[nt][3] = -1e9f;
            }
        }

        // ---- online softmax ----
        float mx0 = -1e30f, mx1 = -1e30f;
#pragma unroll
        for (int nt = 0; nt < 8; nt++) {
            mx0 = fmaxf(mx0, fmaxf(sa[nt][0], sa[nt][1]));
            mx1 = fmaxf(mx1, fmaxf(sa[nt][2], sa[nt][3]));
        }
        mx0 = fmaxf(mx0, __shfl_xor_sync(0xffffffffu, mx0, 1));
        mx0 = fmaxf(mx0, __shfl_xor_sync(0xffffffffu, mx0, 2));
        mx1 = fmaxf(mx1, __shfl_xor_sync(0xffffffffu, mx1, 1));
        mx1 = fmaxf(mx1, __shfl_xor_sync(0xffffffffu, mx1, 2));
        float mn0 = fmaxf(m0, mx0), mn1 = fmaxf(m1, mx1);
        float c0 = __expf(m0 - mn0), c1 = __expf(m1 - mn1);
        float rs0 = 0.f, rs1 = 0.f;
#pragma unroll
        for (int nt = 0; nt < 8; nt++) {
            sa[nt][0] = __expf(sa[nt][0] - mn0); rs0 += sa[nt][0];
            sa[nt][1] = __expf(sa[nt][1] - mn0); rs0 += sa[nt][1];
            sa[nt][2] = __expf(sa[nt][2] - mn1); rs1 += sa[nt][2];
            sa[nt][3] = __expf(sa[nt][3] - mn1); rs1 += sa[nt][3];
        }
        rs0 += __shfl_xor_sync(0xffffffffu, rs0, 1);
        rs0 += __shfl_xor_sync(0xffffffffu, rs0, 2);
        rs1 += __shfl_xor_sync(0xffffffffu, rs1, 1);
        rs1 += __shfl_xor_sync(0xffffffffu, rs1, 2);
        l0 = l0 * c0 + rs0; l1 = l1 * c1 + rs1;
        m0 = mn0; m1 = mn1;
#pragma unroll
        for (int nt = 0; nt < 8; nt++) {
            o[nt][0] *= c0; o[nt][1] *= c0;
            o[nt][2] *= c1; o[nt][3] *= c1;
        }

        // ---- O += P V ----
#pragma unroll
        for (int k2 = 0; k2 < 4; k2++) {
            uint32_t phi[4], plo[4];
            split2(sa[2*k2][0],   sa[2*k2][1],   phi[0], plo[0]);
            split2(sa[2*k2][2],   sa[2*k2][3],   phi[1], plo[1]);
            split2(sa[2*k2+1][0], sa[2*k2+1][1], phi[2], plo[2]);
            split2(sa[2*k2+1][2], sa[2*k2+1][3], phi[3], plo[3]);
#pragma unroll
            for (int u = 0; u < 4; u++) {
                uint32_t voff = swz128((uint32_t)((k2 * 16 + lr) * 128 + u * 32 + lc));
                uint32_t th[4], tl[4];
                ldsm4t(th, sVhi + voff);
                ldsm4t(tl, sVlo + voff);
                mma_bf16(o[2*u],   phi, th[0], th[1]);
                mma_bf16(o[2*u],   phi, tl[0], tl[1]);
                mma_bf16(o[2*u],   plo, th[0], th[1]);
                mma_bf16(o[2*u+1], phi, th[2], th[3]);
                mma_bf16(o[2*u+1], phi, tl[2], tl[3]);
                mma_bf16(o[2*u+1], plo, th[2], th[3]);
            }
        }
    }

    // ---- epilogue ----
    float i0 = 1.f / l0, i1 = 1.f / l1;
    float* O0 = OUT + ((size_t)b_ * Ss + row0) * DM + h_ * HD;
    float* O1 = O0 + 8 * DM;
#pragma unroll
    for (int nt = 0; nt < 8; nt++) {
        int d = nt * 8 + (lane & 3) * 2;
        float2 a; a.x = o[nt][0] * i0; a.y = o[nt][1] * i0;
        float2 b; b.x = o[nt][2] * i1; b.y = o[nt][3] * i1;
        *(float2*)(O0 + d) = a;
        *(float2*)(O1 + d) = b;
    }
}

// ---------------------------------------------------------------------------
extern "C" void kernel_launch(void* const* d_in, const int* in_sizes, int n_in,
                              void* d_out, int out_size)
{
    const float* queries = (const float*)d_in[0];
    const float* keys    = (const float*)d_in[1];
    const float* values  = (const float*)d_in[2];
    // d_in[3] = mask (causal triu) — computed arithmetically instead
    const float* Wq = (const float*)d_in[4];
    const float* bq = (const float*)d_in[5];
    const float* Wk = (const float*)d_in[6];
    const float* bk = (const float*)d_in[7];
    const float* Wv = (const float*)d_in[8];
    const float* bv = (const float*)d_in[9];
    const float* Wo = (const float*)d_in[10];
    const float* bo = (const float*)d_in[11];

    // One-time host setup: cache scratch pointers + smem attributes.
    // (Caches pointers only — every call enqueues identical work.)
    static float* att = nullptr;
    static __nv_bfloat16 *qhi, *qlo, *khi, *klo, *vhi, *vlo;
    static __nv_bfloat16 *bhiQ, *bloQ, *bhiK, *bloK, *bhiV, *bloV, *bhiO, *bloO;
    if (att == nullptr) {
        cudaGetSymbolAddress((void**)&qhi, g_Qhi);
        cudaGetSymbolAddress((void**)&qlo, g_Qlo);
        cudaGetSymbolAddress((void**)&khi, g_Khi);
        cudaGetSymbolAddress((void**)&klo, g_Klo);
        cudaGetSymbolAddress((void**)&vhi, g_Vhi);
        cudaGetSymbolAddress((void**)&vlo, g_Vlo);
        cudaGetSymbolAddress((void**)&att, g_att);
        cudaGetSymbolAddress((void**)&bhiQ, g_BhiQ);
        cudaGetSymbolAddress((void**)&bloQ, g_BloQ);
        cudaGetSymbolAddress((void**)&bhiK, g_BhiK);
        cudaGetSymbolAddress((void**)&bloK, g_BloK);
        cudaGetSymbolAddress((void**)&bhiV, g_BhiV);
        cudaGetSymbolAddress((void**)&bloV, g_BloV);
        cudaGetSymbolAddress((void**)&bhiO, g_BhiO);
        cudaGetSymbolAddress((void**)&bloO, g_BloO);
        cudaFuncSetAttribute(flash_mma,
                             cudaFuncAttributeMaxDynamicSharedMemorySize,
                             FM_SMEM_BYTES);
        cudaFuncSetAttribute(gemm_qkv,
                             cudaFuncAttributeMaxDynamicSharedMemorySize,
                             G_SMEM_TOTAL);
        cudaFuncSetAttribute(gemm_out,
                             cudaFuncAttributeMaxDynamicSharedMemorySize,
                             G_SMEM_TOTAL);
    }

    dim3 wgrid(DM / 32, DM / 32), wblk(32, 8);

    // All weight conversions up front (independent; Wo hidden before flash)
    conv_w_t<<<wgrid, wblk>>>(Wq, bhiQ, bloQ);
    conv_w_t<<<wgrid, wblk>>>(Wk, bhiK, bloK);
    conv_w_t<<<wgrid, wblk>>>(Wv, bhiV, bloV);
    conv_w_t<<<wgrid, wblk>>>(Wo, bhiO, bloO);

    // Fused Q/K/V projections: one launch, 768 CTAs
    gemm_qkv<<<dim3(DM / 128, NROWS / 128, 3), 256, G_SMEM_TOTAL>>>(
        queries, keys, values, bq, bk, bv);

    // Attention (split-bf16 tensor-core flash, pre-split, double-buffered)
    flash_mma<<<dim3(Ss / 128, Bb * Hh), 256, FM_SMEM_BYTES>>>(
        qhi, qlo, khi, klo, vhi, vlo, att);

    // Output projection (fp32 att in, fp32 out)
    gemm_out<<<dim3(DM / 128, NROWS / 128), 256, G_SMEM_TOTAL>>>(
        att, bo, (float*)d_out);
}